// round 9
// baseline (speedup 1.0000x reference)
#include <cuda_runtime.h>
#include <cuda_bf16.h>
#include <math.h>
#include <stdint.h>

// Problem constants (fixed by the reference)
#define NN 50000
#define NE 600000
#define NG 64
#define DH 128
#define DLAT 64

// int8 factorized GEMM: feat@W = h@Wh + agg@W1 + amp*(agg@W2) + att*(agg@W3)
#define NJ 10            // jobs: 2 h-jobs (k64) + 8 agg-jobs (k64, 3 W each)
#define WL 106496        // u32 per layer W image
#define STGU 17920       // u32 per smem stage
#define SMEM_BYTES ((2 * STGU + 512) * 4)

// ---------------- device scratch ------------------------------------------
__device__ int   g_deg[NN];
__device__ int   g_off[NN + 1];
__device__ int   g_cur[NN];
__device__ int   g_csr[NE];
__device__ int   g_bsum[64];
__device__ float g_delta[1];
__device__ float g_h0[(size_t)NN * DH];
__device__ float g_h1[(size_t)NN * DH];
__device__ unsigned g_H8h[(size_t)NN * 32];    // h int8-hi image (4 k/word)
__device__ unsigned g_H8l[(size_t)NN * 32];
__device__ unsigned g_A8h[(size_t)NN * 128];   // agg int8-hi image
__device__ unsigned g_A8l[(size_t)NN * 128];
__device__ float g_sa_h[NN];
__device__ float g_sa_ag[NN];
__device__ float g_sb[3 * 512];
__device__ unsigned g_W[3 * WL];
__device__ float g_pool[NG * DH];

// ---------------- helpers --------------------------------------------------
__device__ __forceinline__ void mma_s8(int* d, const unsigned* a, const unsigned* b) {
    asm volatile(
        "mma.sync.aligned.m16n8k32.row.col.s32.s8.s8.s32 "
        "{%0,%1,%2,%3}, {%4,%5,%6,%7}, {%8,%9}, {%0,%1,%2,%3};\n"
        : "+r"(d[0]), "+r"(d[1]), "+r"(d[2]), "+r"(d[3])
        : "r"(a[0]), "r"(a[1]), "r"(a[2]), "r"(a[3]), "r"(b[0]), "r"(b[1]));
}
__device__ __forceinline__ void ldsm4(unsigned& r0, unsigned& r1,
                                      unsigned& r2, unsigned& r3, uint32_t a) {
    asm volatile("ldmatrix.sync.aligned.m8n8.x4.shared.b16 {%0,%1,%2,%3}, [%4];"
                 : "=r"(r0), "=r"(r1), "=r"(r2), "=r"(r3) : "r"(a));
}
__device__ __forceinline__ uint32_t smem_u32(const void* p) {
    uint32_t a;
    asm("{ .reg .u64 t; cvta.to.shared.u64 t, %1; cvt.u32.u64 %0, t; }"
        : "=r"(a) : "l"(p));
    return a;
}
__device__ __forceinline__ void cp16(uint32_t dst, const void* src) {
    asm volatile("cp.async.cg.shared.global [%0], [%1], 16;"
                 :: "r"(dst), "l"(src));
}
#define CP_COMMIT() asm volatile("cp.async.commit_group;" ::: "memory")
#define CP_WAIT0()  asm volatile("cp.async.wait_group 0;" ::: "memory")

__device__ __forceinline__ void quant2(float v, float inv, int& ah, int& al) {
    int q = __float2int_rn(v * inv);
    q = max(-32512, min(32512, q));
    ah = (q + 128) >> 8;
    al = q - (ah << 8);
}
__device__ __forceinline__ unsigned pack4(int b0, int b1, int b2, int b3) {
    return (b0 & 0xff) | ((b1 & 0xff) << 8) | ((b2 & 0xff) << 16) | ((b3 & 0xff) << 24);
}

// ---------------- graph prep ----------------------------------------------
__global__ void hist_kernel(const int* __restrict__ ei) {
    int e = blockIdx.x * blockDim.x + threadIdx.x;
    int stride = gridDim.x * blockDim.x;
    for (; e < NE; e += stride) atomicAdd(&g_deg[ei[NE + e]], 1);
}

__global__ void scan1_kernel() {
    __shared__ int sh[1024];
    int b = blockIdx.x, t = threadIdx.x;
    int i = b * 1024 + t;
    int v = (i < NN) ? g_deg[i] : 0;
    sh[t] = v;
    __syncthreads();
    #pragma unroll
    for (int s = 1; s < 1024; s <<= 1) {
        int add = (t >= s) ? sh[t - s] : 0;
        __syncthreads();
        sh[t] += add;
        __syncthreads();
    }
    if (i < NN) g_off[i] = sh[t] - v;
    if (t == 1023) g_bsum[b] = sh[1023];
}
__global__ void scan2_kernel(int nblk) {
    if (threadIdx.x == 0) {
        int c = 0;
        for (int b = 0; b < nblk; b++) { int s = g_bsum[b]; g_bsum[b] = c; c += s; }
        g_off[NN] = c;
    }
}
__global__ void scan3_kernel() {
    int i = blockIdx.x * 1024 + threadIdx.x;
    if (i < NN) g_off[i] += g_bsum[blockIdx.x];
}

__global__ void scatter_kernel(const int* __restrict__ ei) {
    int e = blockIdx.x * blockDim.x + threadIdx.x;
    int stride = gridDim.x * blockDim.x;
    for (; e < NE; e += stride) {
        int dst = ei[NE + e];
        int pos = g_off[dst] + atomicAdd(&g_cur[dst], 1);
        g_csr[pos] = ei[e];
    }
}

__global__ void delta_kernel() {
    int i = blockIdx.x * blockDim.x + threadIdx.x;
    int stride = gridDim.x * blockDim.x;
    float s = 0.f;
    for (; i < NN; i += stride) s += logf((float)g_deg[i] + 1.f);
    #pragma unroll
    for (int o = 16; o > 0; o >>= 1) s += __shfl_down_sync(0xffffffffu, s, o);
    __shared__ float sh[32];
    int lane = threadIdx.x & 31, wid = threadIdx.x >> 5;
    if (lane == 0) sh[wid] = s;
    __syncthreads();
    if (wid == 0) {
        float v = (lane < (int)(blockDim.x >> 5)) ? sh[lane] : 0.f;
        #pragma unroll
        for (int o = 16; o > 0; o >>= 1) v += __shfl_down_sync(0xffffffffu, v, o);
        if (lane == 0) atomicAdd(&g_delta[0], v);
    }
}

// ---------------- W scales + quantized image --------------------------------
__global__ void wscale_kernel(const float* __restrict__ W, float* __restrict__ sb) {
    int seg = blockIdx.x, t = threadIdx.x;
    int r0 = (seg == 0) ? 0 : 128 + (seg - 1) * 512;
    int nr = (seg == 0) ? 128 : 512;
    float m = 0.f;
    for (int r = 0; r < nr; r++)
        m = fmaxf(m, fabsf(W[(size_t)(r0 + r) * DH + t]));
    sb[seg * 128 + t] = fmaxf(m, 1e-30f) * (1.f / 32512.f);
}

// image layout per layer: h-jobs j=0,1 at j*4096 (hi, lo@+2048);
// agg jobs j2=0..7 at 8192 + j2*12288 + w*4096.  Each buffer: [n=128][c=16] u32.
__global__ void wquant_kernel(const float* __restrict__ W,
                              const float* __restrict__ sb,
                              unsigned* __restrict__ img) {
    int i = blockIdx.x * blockDim.x + threadIdx.x;
    if (i >= 53248) return;
    int n, c, kr, sbi, base;
    if (i < 4096) {
        int j = i >> 11, rem = i & 2047;
        n = rem >> 4; c = rem & 15;
        kr = j * 64 + c * 4; sbi = n; base = j * 4096;
    } else {
        int p = i - 4096;
        int j2 = p / 6144, q = p % 6144;
        int w = q >> 11; int rem = q & 2047;
        n = rem >> 4; c = rem & 15;
        kr = 128 + w * 512 + j2 * 64 + c * 4;
        sbi = (w + 1) * 128 + n;
        base = 8192 + j2 * 12288 + w * 4096;
    }
    float inv = 1.f / sb[sbi];
    int ah[4], al[4];
    #pragma unroll
    for (int r = 0; r < 4; r++)
        quant2(W[(size_t)(kr + r) * DH + n], inv, ah[r], al[r]);
    img[base + n * 16 + c] = pack4(ah[0], ah[1], ah[2], ah[3]);
    img[base + 2048 + n * 16 + c] = pack4(al[0], al[1], al[2], al[3]);
}

// ---------------- h / x quantization ----------------------------------------
__global__ __launch_bounds__(128) void hquant_kernel(const float* __restrict__ h) {
    int n = blockIdx.x, t = threadIdx.x;
    __shared__ float red[128];
    __shared__ int qs[128];
    float v = h[(size_t)n * DH + t];
    red[t] = fabsf(v);
    __syncthreads();
    for (int s = 64; s > 0; s >>= 1) {
        if (t < s) red[t] = fmaxf(red[t], red[t + s]);
        __syncthreads();
    }
    float mx = fmaxf(red[0], 1e-30f);
    float inv = 32512.f / mx;
    int q = __float2int_rn(v * inv);
    qs[t] = max(-32512, min(32512, q));
    if (t == 0) g_sa_h[n] = mx * (1.f / 32512.f);
    __syncthreads();
    if (t < 32) {
        int a_[4], l_[4];
        #pragma unroll
        for (int i = 0; i < 4; i++) {
            int qq = qs[4 * t + i];
            a_[i] = (qq + 128) >> 8;
            l_[i] = qq - (a_[i] << 8);
        }
        g_H8h[(size_t)n * 32 + t] = pack4(a_[0], a_[1], a_[2], a_[3]);
        g_H8l[(size_t)n * 32 + t] = pack4(l_[0], l_[1], l_[2], l_[3]);
    }
}

// ---------------- aggregation -> int8 agg image -----------------------------
__global__ __launch_bounds__(128) void agg_kernel(const float* __restrict__ h) {
    int n = blockIdx.x;
    int t = threadIdx.x;
    int beg = g_off[n], end = g_off[n + 1];
    int d = end - beg;
    float s = 0.f, ss = 0.f;
    float mx = __int_as_float(0xff800000);
    float mn = __int_as_float(0x7f800000);
    __shared__ int ssrc[128];
    for (int base = beg; base < end; base += 128) {
        int cnt = min(128, end - base);
        if (t < cnt) ssrc[t] = g_csr[base + t];
        __syncthreads();
        #pragma unroll 4
        for (int i = 0; i < cnt; i++) {
            float m = h[(size_t)ssrc[i] * DH + t];
            s += m; ss += m * m;
            mx = fmaxf(mx, m); mn = fminf(mn, m);
        }
        __syncthreads();
    }
    float cntf = fmaxf((float)d, 1.f);
    float mean = s / cntf;
    float var = fmaxf(ss / cntf - mean * mean, 0.f);
    float stdv = sqrtf(var + 1e-5f);
    if (d == 0) { mx = 0.f; mn = 0.f; }

    __shared__ float sf[512];
    __shared__ float red[128];
    sf[t] = mean;
    sf[128 + t] = mx;
    sf[256 + t] = mn;
    sf[384 + t] = stdv;
    __syncthreads();

    float am = 0.f;
    #pragma unroll
    for (int i = 0; i < 4; i++) am = fmaxf(am, fabsf(sf[4 * t + i]));
    red[t] = am;
    __syncthreads();
    for (int sdx = 64; sdx > 0; sdx >>= 1) {
        if (t < sdx) red[t] = fmaxf(red[t], red[t + sdx]);
        __syncthreads();
    }
    float rmx = fmaxf(red[0], 1e-30f);
    if (t == 0) g_sa_ag[n] = rmx * (1.f / 32512.f);
    float inv = 32512.f / rmx;
    int a_[4], l_[4];
    #pragma unroll
    for (int i = 0; i < 4; i++) quant2(sf[4 * t + i], inv, a_[i], l_[i]);
    g_A8h[(size_t)n * 128 + t] = pack4(a_[0], a_[1], a_[2], a_[3]);
    g_A8l[(size_t)n * 128 + t] = pack4(l_[0], l_[1], l_[2], l_[3]);
}

// ---------------- int8 factorized GEMM --------------------------------------
// block 64m x 128n, 256 threads (8 warps 2m x 4n), warp tile 32x32.
// stage (u32): A hi[64][20]@0, lo@1280; B @2560: w*5120 + {hi, lo@+2560}[128][20]
__global__ __launch_bounds__(256) void gemm_i8_kernel(
        const unsigned* __restrict__ Wimg, const float* __restrict__ sbL,
        const float* __restrict__ bias, float* __restrict__ hout) {
    extern __shared__ unsigned smem_u[];
    const uint32_t sbase = smem_u32(smem_u);
    float* sb_s = (float*)(smem_u + 2 * STGU);
    int tid = threadIdx.x;
    for (int i = tid; i < 512; i += 256) sb_s[i] = sbL[i];

    const int lane = tid & 31, wid = tid >> 5;
    const int warp_m = wid >> 2;   // 0..1
    const int warp_n = wid & 3;    // 0..3
    const int lr = lane >> 2, lc = lane & 3;
    const int row0 = blockIdx.x * 64;
    const int lg = lane >> 3, l8 = lane & 7;
    const int a_row = ((lg & 1) << 3) + l8;
    const int a_col = (lg >> 1) << 2;
    const int b_row = ((lg >> 1) << 3) + l8;
    const int b_col = (lg & 1) << 2;
    const int a_base = (warp_m * 32 + a_row) * 20 + a_col;
    const int b_base = 2560 + (warp_n * 32 + b_row) * 20 + b_col;

    float F[3][2][4][4];
    #pragma unroll
    for (int g = 0; g < 3; g++)
        #pragma unroll
        for (int mt = 0; mt < 2; mt++)
            #pragma unroll
            for (int nt = 0; nt < 4; nt++)
                #pragma unroll
                for (int e = 0; e < 4; e++) F[g][mt][nt][e] = 0.f;

    float saH[2][2], saA[2][2];
    #pragma unroll
    for (int mt = 0; mt < 2; mt++)
        #pragma unroll
        for (int rh = 0; rh < 2; rh++) {
            int rr = row0 + warp_m * 32 + mt * 16 + lr + rh * 8;
            int ri = min(rr, NN - 1);
            saH[mt][rh] = g_sa_h[ri];
            saA[mt][rh] = g_sa_ag[ri];
        }

    auto load_stage = [&](int j, int slot) {
        uint32_t base = sbase + slot * (STGU * 4);
        int isH = (j < 2);
        int nW = isH ? 1 : 3;
        int koff = isH ? j * 16 : (j - 2) * 16;
        int K2 = isH ? 32 : 128;
        const unsigned* Ah = isH ? g_H8h : g_A8h;
        const unsigned* Al = isH ? g_H8l : g_A8l;
        const unsigned* Bsrc = Wimg + (isH ? (size_t)j * 4096
                                           : (size_t)8192 + (size_t)(j - 2) * 12288);
        int nch = 512 + nW * 1024;
        for (int c = tid; c < nch; c += 256) {
            uint32_t dst;
            const unsigned* src;
            if (c < 512) {
                int half = (c >= 256) ? 1 : 0;
                int rem = c - half * 256;
                int r = rem >> 2, q = rem & 3;
                int node = row0 + r;
                if (node >= NN) node = NN - 1;
                src = (half ? Al : Ah) + (size_t)node * K2 + koff + q * 4;
                dst = base + (half * 1280 + r * 20 + q * 4) * 4;
            } else {
                int cb = c - 512;
                int w = cb >> 10;
                int rem = cb & 1023;
                int half = (rem >= 512) ? 1 : 0;
                int rem2 = rem - half * 512;
                int r = rem2 >> 2, q = rem2 & 3;
                src = Bsrc + w * 4096 + half * 2048 + r * 16 + q * 4;
                dst = base + (2560 + w * 5120 + half * 2560 + r * 20 + q * 4) * 4;
            }
            cp16(dst, src);
        }
        CP_COMMIT();
    };

    load_stage(0, 0);

    for (int j = 0; j < NJ; j++) {
        CP_WAIT0();
        __syncthreads();
        if (j + 1 < NJ) load_stage(j + 1, (j + 1) & 1);

        uint32_t st = sbase + (j & 1) * (STGU * 4);
        int nW = (j < 2) ? 1 : 3;

        // A fragments for both k32 steps (hi and lo)
        unsigned ah[2][2][4], al[2][2][4];
        #pragma unroll
        for (int kb2 = 0; kb2 < 2; kb2++)
            #pragma unroll
            for (int mt = 0; mt < 2; mt++) {
                uint32_t ad = st + (uint32_t)(a_base + mt * 320 + kb2 * 8) * 4;
                ldsm4(ah[kb2][mt][0], ah[kb2][mt][1], ah[kb2][mt][2], ah[kb2][mt][3], ad);
                ldsm4(al[kb2][mt][0], al[kb2][mt][1], al[kb2][mt][2], al[kb2][mt][3],
                      ad + 1280 * 4);
            }

        for (int w = 0; w < nW; w++) {
            int H[2][4][4], X[2][4][4];
            #pragma unroll
            for (int mt = 0; mt < 2; mt++)
                #pragma unroll
                for (int nt = 0; nt < 4; nt++)
                    #pragma unroll
                    for (int e = 0; e < 4; e++) { H[mt][nt][e] = 0; X[mt][nt][e] = 0; }

            #pragma unroll
            for (int kb2 = 0; kb2 < 2; kb2++) {
                uint32_t bd = st + (uint32_t)(b_base + w * 5120 + kb2 * 8) * 4;
                #pragma unroll
                for (int p = 0; p < 2; p++) {
                    unsigned bh[4], bl[4];
                    uint32_t bp = bd + (uint32_t)(p * 320) * 4;
                    ldsm4(bh[0], bh[1], bh[2], bh[3], bp);
                    ldsm4(bl[0], bl[1], bl[2], bl[3], bp + 2560 * 4);
                    #pragma unroll
                    for (int q = 0; q < 2; q++) {
                        int nt = 2 * p + q;
                        #pragma unroll
                        for (int mt = 0; mt < 2; mt++) {
                            mma_s8(H[mt][nt], ah[kb2][mt], &bh[2 * q]);
                            mma_s8(X[mt][nt], ah[kb2][mt], &bl[2 * q]);
                            mma_s8(X[mt][nt], al[kb2][mt], &bh[2 * q]);
                        }
                    }
                }
            }
            // fold into float accumulators with scales
            int g = (j < 2) ? 0 : w;
            int wsel = (j < 2) ? 0 : (w + 1);
            #pragma unroll
            for (int mt = 0; mt < 2; mt++)
                #pragma unroll
                for (int nt = 0; nt < 4; nt++) {
                    int col0 = warp_n * 32 + nt * 8 + 2 * lc;
                    float s0 = sb_s[wsel * 128 + col0];
                    float s1 = sb_s[wsel * 128 + col0 + 1];
                    #pragma unroll
                    for (int e = 0; e < 4; e++) {
                        float sa_ = (j < 2) ? saH[mt][e >> 1] : saA[mt][e >> 1];
                        float cs = sa_ * ((e & 1) ? s1 : s0);
                        float tv = 65536.f * (float)H[mt][nt][e]
                                 + 256.f * (float)X[mt][nt][e];
                        F[g][mt][nt][e] = fmaf(cs, tv, F[g][mt][nt][e]);
                    }
                }
        }
        __syncthreads();
    }

    // ---- epilogue: combine groups, bias, relu ----
    float dlt = g_delta[0] * (1.f / (float)NN);
    float ampv[2][2], attv[2][2];
    #pragma unroll
    for (int mt = 0; mt < 2; mt++)
        #pragma unroll
        for (int rh = 0; rh < 2; rh++) {
            int row = row0 + warp_m * 32 + mt * 16 + lr + rh * 8;
            float a = 0.f, b = 0.f;
            if (row < NN) {
                float logd = logf((float)g_deg[row] + 1.f);
                a = logd / dlt;
                b = dlt / fmaxf(logd, 1e-5f);
            }
            ampv[mt][rh] = a;
            attv[mt][rh] = b;
        }

    #pragma unroll
    for (int mt = 0; mt < 2; mt++)
        #pragma unroll
        for (int nt = 0; nt < 4; nt++) {
            int col0 = warp_n * 32 + nt * 8 + 2 * lc;
            float b0 = bias[col0], b1 = bias[col0 + 1];
            #pragma unroll
            for (int rh = 0; rh < 2; rh++) {
                int row = row0 + warp_m * 32 + mt * 16 + lr + rh * 8;
                if (row >= NN) continue;
                float amp = ampv[mt][rh], att = attv[mt][rh];
                int e0 = rh * 2;
                float2 v;
                v.x = fmaxf(F[0][mt][nt][e0] + amp * F[1][mt][nt][e0]
                            + att * F[2][mt][nt][e0] + b0, 0.f);
                v.y = fmaxf(F[0][mt][nt][e0 + 1] + amp * F[1][mt][nt][e0 + 1]
                            + att * F[2][mt][nt][e0 + 1] + b1, 0.f);
                *(float2*)&hout[(size_t)row * DH + col0] = v;
            }
        }
}

// ---------------- pooling + bn/fc --------------------------------------------
#define POOL_NB 256
__global__ __launch_bounds__(128) void pool_kernel(
        const float* __restrict__ h, const int* __restrict__ batch) {
    int n0 = blockIdx.x * POOL_NB;
    int t = threadIdx.x;
    int nend = min(n0 + POOL_NB, NN);
    int cnt = nend - n0;
    __shared__ int sbm[POOL_NB];
    for (int i = t; i < cnt; i += 128) sbm[i] = batch[n0 + i];
    __syncthreads();
    float acc = 0.f;
    int cur = sbm[0];
    for (int i = 0; i < cnt; i++) {
        int b = sbm[i];
        if (b != cur) {
            atomicAdd(&g_pool[cur * DH + t], acc);
            acc = 0.f; cur = b;
        }
        acc += h[(size_t)(n0 + i) * DH + t];
    }
    atomicAdd(&g_pool[cur * DH + t], acc);
}

__global__ __launch_bounds__(128) void bnfc_kernel(
        const float* __restrict__ gamma, const float* __restrict__ beta,
        const float* __restrict__ fcW, const float* __restrict__ fcb,
        float* __restrict__ out) {
    __shared__ float sp[NG * DH];
    int t = threadIdx.x;
    for (int i = t; i < NG * DH; i += 128) sp[i] = g_pool[i];
    __syncthreads();
    float m = 0.f;
    #pragma unroll 4
    for (int g = 0; g < NG; g++) m += sp[g * DH + t];
    m *= (1.f / NG);
    float v = 0.f;
    #pragma unroll 4
    for (int g = 0; g < NG; g++) { float d = sp[g * DH + t] - m; v += d * d; }
    v *= (1.f / NG);
    float rs = rsqrtf(v + 1e-5f);
    float ga = gamma[t], be = beta[t];
    for (int g = 0; g < NG; g++)
        sp[g * DH + t] = (sp[g * DH + t] - m) * rs * ga + be;
    __syncthreads();
    for (int i = t; i < NG * DLAT; i += 128) {
        int g = i / DLAT, jj = i % DLAT;
        float s = fcb[jj];
        #pragma unroll 8
        for (int c = 0; c < DH; c++) s += sp[g * DH + c] * fcW[c * DLAT + jj];
        out[i] = s;
    }
}

// ---------------- launch ------------------------------------------------------
extern "C" void kernel_launch(void* const* d_in, const int* in_sizes, int n_in,
                              void* d_out, int out_size) {
    const float* x     = (const float*)d_in[0];
    const int*   ei    = (const int*)d_in[1];
    const int*   batch = (const int*)d_in[2];
    const float* W0 = (const float*)d_in[3];  const float* b0 = (const float*)d_in[4];
    const float* W1 = (const float*)d_in[5];  const float* b1 = (const float*)d_in[6];
    const float* W2 = (const float*)d_in[7];  const float* b2 = (const float*)d_in[8];
    const float* gamma = (const float*)d_in[9];
    const float* beta  = (const float*)d_in[10];
    const float* fcW   = (const float*)d_in[11];
    const float* fcb   = (const float*)d_in[12];
    float* out = (float*)d_out;

    void *p_deg, *p_cur, *p_delta, *p_pool, *p_h0, *p_h1, *p_w, *p_sb;
    cudaGetSymbolAddress(&p_deg,   g_deg);
    cudaGetSymbolAddress(&p_cur,   g_cur);
    cudaGetSymbolAddress(&p_delta, g_delta);
    cudaGetSymbolAddress(&p_pool,  g_pool);
    cudaGetSymbolAddress(&p_h0,    g_h0);
    cudaGetSymbolAddress(&p_h1,    g_h1);
    cudaGetSymbolAddress(&p_w,     g_W);
    cudaGetSymbolAddress(&p_sb,    g_sb);
    float* h0 = (float*)p_h0;
    float* h1 = (float*)p_h1;
    unsigned* wimg = (unsigned*)p_w;
    float* sb = (float*)p_sb;

    cudaFuncSetAttribute(gemm_i8_kernel,
                         cudaFuncAttributeMaxDynamicSharedMemorySize, SMEM_BYTES);

    cudaMemsetAsync(p_deg,   0, NN * sizeof(int));
    cudaMemsetAsync(p_cur,   0, NN * sizeof(int));
    cudaMemsetAsync(p_delta, 0, sizeof(float));
    cudaMemsetAsync(p_pool,  0, NG * DH * sizeof(float));

    const float* Ws[3] = {W0, W1, W2};
    for (int l = 0; l < 3; l++) {
        wscale_kernel<<<4, 128>>>(Ws[l], sb + l * 512);
        wquant_kernel<<<(53248 + 255) / 256, 256>>>(Ws[l], sb + l * 512, wimg + (size_t)l * WL);
    }

    int eblocks = (NE + 1023) / 1024;
    int sblocks = (NN + 1023) / 1024;
    hist_kernel<<<eblocks, 1024>>>(ei);
    scan1_kernel<<<sblocks, 1024>>>();
    scan2_kernel<<<1, 32>>>(sblocks);
    scan3_kernel<<<sblocks, 1024>>>();
    scatter_kernel<<<eblocks, 1024>>>(ei);
    delta_kernel<<<128, 256>>>();

    int gblocks = (NN + 63) / 64;   // 782

    // layer 0
    hquant_kernel<<<NN, 128>>>(x);
    agg_kernel<<<NN, 128>>>(x);
    gemm_i8_kernel<<<gblocks, 256, SMEM_BYTES>>>(wimg, sb, b0, h0);
    // layer 1
    hquant_kernel<<<NN, 128>>>(h0);
    agg_kernel<<<NN, 128>>>(h0);
    gemm_i8_kernel<<<gblocks, 256, SMEM_BYTES>>>(wimg + WL, sb + 512, b1, h1);
    // layer 2
    hquant_kernel<<<NN, 128>>>(h1);
    agg_kernel<<<NN, 128>>>(h1);
    gemm_i8_kernel<<<gblocks, 256, SMEM_BYTES>>>(wimg + 2 * (size_t)WL, sb + 1024, b2, h0);

    pool_kernel<<<(NN + POOL_NB - 1) / POOL_NB, 128>>>(h0, batch);
    bnfc_kernel<<<1, 128>>>(gamma, beta, fcW, fcb, out);
}

// round 10
// speedup vs baseline: 1.0079x; 1.0079x over previous
#include <cuda_runtime.h>
#include <cuda_bf16.h>
#include <math.h>
#include <stdint.h>

// Problem constants (fixed by the reference)
#define NN 50000
#define NE 600000
#define NG 64
#define DH 128
#define DLAT 64

// int8 factorized GEMM: feat@W = h@Wh + agg@W1 + amp*(agg@W2) + att*(agg@W3)
// 26 jobs/block: seg0(h,K=128): 2 k64 jobs; segs1-4 (agg): 4 x 3w x 2 k64.
#define NJ 26
#define WL 106496        // u32 per layer W image (26 * 4096)
#define STGU 7680        // u32 per smem stage: A 2*64*20 + B 2*128*20
#define SMEM_BYTES ((2 * STGU + 13 * 128) * 4)

// ---------------- device scratch ------------------------------------------
__device__ int   g_deg[NN];
__device__ int   g_off[NN + 1];
__device__ int   g_cur[NN];
__device__ int   g_csr[NE];
__device__ int   g_bsum[64];
__device__ float g_delta[1];
__device__ float g_h0[(size_t)NN * DH];
__device__ float g_h1[(size_t)NN * DH];
__device__ unsigned g_H8h[(size_t)NN * 32];    // h int8-hi image (4 k/u32)
__device__ unsigned g_H8l[(size_t)NN * 32];
__device__ unsigned g_A8h[(size_t)NN * 128];   // agg int8-hi image
__device__ unsigned g_A8l[(size_t)NN * 128];
__device__ float g_sa[(size_t)5 * NN];         // per (segment, row) A scales
__device__ float g_sb[3 * 13 * 128];           // per (layer, segw, col) B scales
__device__ unsigned g_W[3 * WL];
__device__ float g_pool[NG * DH];

// ---------------- helpers --------------------------------------------------
__device__ __forceinline__ void mma_s8(int* d, const unsigned* a, const unsigned* b) {
    asm volatile(
        "mma.sync.aligned.m16n8k32.row.col.s32.s8.s8.s32 "
        "{%0,%1,%2,%3}, {%4,%5,%6,%7}, {%8,%9}, {%0,%1,%2,%3};\n"
        : "+r"(d[0]), "+r"(d[1]), "+r"(d[2]), "+r"(d[3])
        : "r"(a[0]), "r"(a[1]), "r"(a[2]), "r"(a[3]), "r"(b[0]), "r"(b[1]));
}
__device__ __forceinline__ void ldsm4(unsigned& r0, unsigned& r1,
                                      unsigned& r2, unsigned& r3, uint32_t a) {
    asm volatile("ldmatrix.sync.aligned.m8n8.x4.shared.b16 {%0,%1,%2,%3}, [%4];"
                 : "=r"(r0), "=r"(r1), "=r"(r2), "=r"(r3) : "r"(a));
}
__device__ __forceinline__ uint32_t smem_u32(const void* p) {
    uint32_t a;
    asm("{ .reg .u64 t; cvta.to.shared.u64 t, %1; cvt.u32.u64 %0, t; }"
        : "=r"(a) : "l"(p));
    return a;
}
__device__ __forceinline__ void cp16(uint32_t dst, const void* src) {
    asm volatile("cp.async.cg.shared.global [%0], [%1], 16;"
                 :: "r"(dst), "l"(src));
}
#define CP_COMMIT() asm volatile("cp.async.commit_group;" ::: "memory")
#define CP_WAIT0()  asm volatile("cp.async.wait_group 0;" ::: "memory")

__device__ __forceinline__ void quant2(float v, float inv, int& ah, int& al) {
    int q = __float2int_rn(v * inv);
    q = max(-32512, min(32512, q));
    ah = (q + 128) >> 8;
    al = q - (ah << 8);
}
__device__ __forceinline__ unsigned pack4(int b0, int b1, int b2, int b3) {
    return (b0 & 0xff) | ((b1 & 0xff) << 8) | ((b2 & 0xff) << 16) | ((b3 & 0xff) << 24);
}

// ---------------- graph prep ----------------------------------------------
__global__ void hist_kernel(const int* __restrict__ ei) {
    int e = blockIdx.x * blockDim.x + threadIdx.x;
    int stride = gridDim.x * blockDim.x;
    for (; e < NE; e += stride) atomicAdd(&g_deg[ei[NE + e]], 1);
}

__global__ void scan1_kernel() {
    __shared__ int sh[1024];
    int b = blockIdx.x, t = threadIdx.x;
    int i = b * 1024 + t;
    int v = (i < NN) ? g_deg[i] : 0;
    sh[t] = v;
    __syncthreads();
    #pragma unroll
    for (int s = 1; s < 1024; s <<= 1) {
        int add = (t >= s) ? sh[t - s] : 0;
        __syncthreads();
        sh[t] += add;
        __syncthreads();
    }
    if (i < NN) g_off[i] = sh[t] - v;
    if (t == 1023) g_bsum[b] = sh[1023];
}
__global__ void scan2_kernel(int nblk) {
    if (threadIdx.x == 0) {
        int c = 0;
        for (int b = 0; b < nblk; b++) { int s = g_bsum[b]; g_bsum[b] = c; c += s; }
        g_off[NN] = c;
    }
}
__global__ void scan3_kernel() {
    int i = blockIdx.x * 1024 + threadIdx.x;
    if (i < NN) g_off[i] += g_bsum[blockIdx.x];
}

__global__ void scatter_kernel(const int* __restrict__ ei) {
    int e = blockIdx.x * blockDim.x + threadIdx.x;
    int stride = gridDim.x * blockDim.x;
    for (; e < NE; e += stride) {
        int dst = ei[NE + e];
        int pos = g_off[dst] + atomicAdd(&g_cur[dst], 1);
        g_csr[pos] = ei[e];
    }
}

__global__ void delta_kernel() {
    int i = blockIdx.x * blockDim.x + threadIdx.x;
    int stride = gridDim.x * blockDim.x;
    float s = 0.f;
    for (; i < NN; i += stride) s += logf((float)g_deg[i] + 1.f);
    #pragma unroll
    for (int o = 16; o > 0; o >>= 1) s += __shfl_down_sync(0xffffffffu, s, o);
    __shared__ float sh[32];
    int lane = threadIdx.x & 31, wid = threadIdx.x >> 5;
    if (lane == 0) sh[wid] = s;
    __syncthreads();
    if (wid == 0) {
        float v = (lane < (int)(blockDim.x >> 5)) ? sh[lane] : 0.f;
        #pragma unroll
        for (int o = 16; o > 0; o >>= 1) v += __shfl_down_sync(0xffffffffu, v, o);
        if (lane == 0) atomicAdd(&g_delta[0], v);
    }
}

// ---------------- W scales + quantized image --------------------------------
// segw 0: W rows 0..127 (h). segw 1+3*s1+w: rows 128 + 512w + 128*s1 .. +127.
__global__ void wscale_kernel(const float* __restrict__ W, float* __restrict__ sb) {
    int bi = blockIdx.x, t = threadIdx.x;
    int r0 = (bi == 0) ? 0 : 128 + 512 * ((bi - 1) % 3) + 128 * ((bi - 1) / 3);
    float m = 0.f;
    for (int r = 0; r < 128; r++)
        m = fmaxf(m, fabsf(W[(size_t)(r0 + r) * DH + t]));
    sb[bi * 128 + t] = fmaxf(m, 1e-30f) * (1.f / 32512.f);
}

// buffer j (job order) at j*4096: hi [n=128][c=16] u32, lo at +2048.
__global__ void wquant_kernel(const float* __restrict__ W,
                              const float* __restrict__ sb,
                              unsigned* __restrict__ img) {
    int i = blockIdx.x * blockDim.x + threadIdx.x;
    if (i >= NJ * 2048) return;
    int j = i >> 11, rem = i & 2047;
    int n = rem >> 4, c = rem & 15;
    int kr0, segw;
    if (j < 2) { kr0 = j * 64; segw = 0; }
    else {
        int p = j - 2;
        int s1 = p / 6, w = (p % 6) >> 1, kt = p & 1;
        kr0 = 128 + 512 * w + 128 * s1 + 64 * kt;
        segw = 1 + s1 * 3 + w;
    }
    float inv = 1.f / sb[segw * 128 + n];
    int ah[4], al[4];
    #pragma unroll
    for (int r = 0; r < 4; r++)
        quant2(W[(size_t)(kr0 + 4 * c + r) * DH + n], inv, ah[r], al[r]);
    img[(size_t)j * 4096 + n * 16 + c] = pack4(ah[0], ah[1], ah[2], ah[3]);
    img[(size_t)j * 4096 + 2048 + n * 16 + c] = pack4(al[0], al[1], al[2], al[3]);
}

// ---------------- h / x quantization (segment 0) -----------------------------
__global__ __launch_bounds__(128) void hquant_kernel(const float* __restrict__ h) {
    int n = blockIdx.x, t = threadIdx.x;
    __shared__ float red[128];
    __shared__ int qs[128];
    float v = h[(size_t)n * DH + t];
    red[t] = fabsf(v);
    __syncthreads();
    for (int s = 64; s > 0; s >>= 1) {
        if (t < s) red[t] = fmaxf(red[t], red[t + s]);
        __syncthreads();
    }
    float mx = fmaxf(red[0], 1e-30f);
    float inv = 32512.f / mx;
    int q = __float2int_rn(v * inv);
    qs[t] = max(-32512, min(32512, q));
    if (t == 0) g_sa[n] = mx * (1.f / 32512.f);
    __syncthreads();
    if (t < 32) {
        int a_[4], l_[4];
        #pragma unroll
        for (int i = 0; i < 4; i++) {
            int qq = qs[4 * t + i];
            a_[i] = (qq + 128) >> 8;
            l_[i] = qq - (a_[i] << 8);
        }
        g_H8h[(size_t)n * 32 + t] = pack4(a_[0], a_[1], a_[2], a_[3]);
        g_H8l[(size_t)n * 32 + t] = pack4(l_[0], l_[1], l_[2], l_[3]);
    }
}

// ---------------- aggregation -> int8 agg image, per-segment scales ----------
__global__ __launch_bounds__(128) void agg_kernel(const float* __restrict__ h) {
    int n = blockIdx.x;
    int t = threadIdx.x;
    int beg = g_off[n], end = g_off[n + 1];
    int d = end - beg;
    float s = 0.f, ss = 0.f;
    float mx = __int_as_float(0xff800000);
    float mn = __int_as_float(0x7f800000);
    __shared__ int ssrc[128];
    for (int base = beg; base < end; base += 128) {
        int cnt = min(128, end - base);
        if (t < cnt) ssrc[t] = g_csr[base + t];
        __syncthreads();
        #pragma unroll 4
        for (int i = 0; i < cnt; i++) {
            float m = h[(size_t)ssrc[i] * DH + t];
            s += m; ss += m * m;
            mx = fmaxf(mx, m); mn = fminf(mn, m);
        }
        __syncthreads();
    }
    float cntf = fmaxf((float)d, 1.f);
    float mean = s / cntf;
    float var = fmaxf(ss / cntf - mean * mean, 0.f);
    float stdv = sqrtf(var + 1e-5f);
    if (d == 0) { mx = 0.f; mn = 0.f; }

    __shared__ float sf[512];
    __shared__ float invs[4];
    sf[t] = mean;
    sf[128 + t] = mx;
    sf[256 + t] = mn;
    sf[384 + t] = stdv;
    __syncthreads();

    // warp w reduces segment w (128 values, 4 per lane)
    {
        int wseg = t >> 5, ln = t & 31;
        float am = 0.f;
        #pragma unroll
        for (int i = 0; i < 4; i++)
            am = fmaxf(am, fabsf(sf[wseg * 128 + ln * 4 + i]));
        #pragma unroll
        for (int o = 16; o > 0; o >>= 1)
            am = fmaxf(am, __shfl_down_sync(0xffffffffu, am, o));
        if (ln == 0) {
            float r = fmaxf(am, 1e-30f);
            g_sa[(size_t)(wseg + 1) * NN + n] = r * (1.f / 32512.f);
            invs[wseg] = 32512.f / r;
        }
    }
    __syncthreads();

    float inv = invs[t >> 5];     // word t covers features 4t..4t+3, seg = t/32
    int a_[4], l_[4];
    #pragma unroll
    for (int i = 0; i < 4; i++) quant2(sf[4 * t + i], inv, a_[i], l_[i]);
    g_A8h[(size_t)n * 128 + t] = pack4(a_[0], a_[1], a_[2], a_[3]);
    g_A8l[(size_t)n * 128 + t] = pack4(l_[0], l_[1], l_[2], l_[3]);
}

// ---------------- int8 factorized GEMM --------------------------------------
// block 64m x 128n, 512 threads (16 warps 4m x 4n), warp tile 16x32 (mt=1).
// stage (u32): A hi[64][20]@0 lo@1280; B hi[128][20]@2560 lo@5120.
__global__ __launch_bounds__(512, 1) void gemm_i8_kernel(
        const unsigned* __restrict__ Wimg, const float* __restrict__ sbL,
        const float* __restrict__ bias, float* __restrict__ hout) {
    extern __shared__ unsigned smem_u[];
    const uint32_t sbase = smem_u32(smem_u);
    float* sb_s = (float*)(smem_u + 2 * STGU);
    const int tid = threadIdx.x;
    for (int i = tid; i < 13 * 128; i += 512) sb_s[i] = sbL[i];

    const int lane = tid & 31, wid = tid >> 5;
    const int warp_m = wid >> 2;   // 0..3 (16 rows each)
    const int warp_n = wid & 3;    // 0..3 (32 cols each)
    const int lr = lane >> 2, lc = lane & 3;
    const int row0 = blockIdx.x * 64;
    const int lg = lane >> 3, l8 = lane & 7;
    const int a_row = ((lg & 1) << 3) + l8;
    const int a_col = (lg >> 1) << 2;
    const int b_row = ((lg >> 1) << 3) + l8;
    const int b_col = (lg & 1) << 2;
    const int a_base = (warp_m * 16 + a_row) * 20 + a_col;
    const int b_base = 2560 + (warp_n * 32 + b_row) * 20 + b_col;

    const int ri0 = min(row0 + warp_m * 16 + lr, NN - 1);
    const int ri1 = min(row0 + warp_m * 16 + lr + 8, NN - 1);

    float F[3][4][4];
    #pragma unroll
    for (int g = 0; g < 3; g++)
        #pragma unroll
        for (int nt = 0; nt < 4; nt++)
            #pragma unroll
            for (int e = 0; e < 4; e++) F[g][nt][e] = 0.f;

    auto load_stage = [&](int j, int slot) {
        uint32_t base = sbase + slot * (STGU * 4);
        const unsigned *Ah, *Al;
        int K2, coff;
        if (j < 2) { Ah = g_H8h; Al = g_H8l; K2 = 32; coff = j * 16; }
        else {
            int p = j - 2;
            int s1 = p / 6, kt = p & 1;
            Ah = g_A8h; Al = g_A8l; K2 = 128;
            coff = s1 * 32 + kt * 16;
        }
        const unsigned* Bsrc = Wimg + (size_t)j * 4096;
        #pragma unroll
        for (int c0 = 0; c0 < 3; c0++) {
            int c = c0 * 512 + tid;
            uint32_t dst;
            const unsigned* src;
            if (c < 512) {
                int half = (c >= 256) ? 1 : 0;
                int rem = c - half * 256;
                int r = rem >> 2, q = rem & 3;
                int node = min(row0 + r, NN - 1);
                src = (half ? Al : Ah) + (size_t)node * K2 + coff + q * 4;
                dst = base + (half * 1280 + r * 20 + q * 4) * 4;
            } else {
                int cb = c - 512;
                int half = cb >> 9;
                int rem = cb & 511;
                int r = rem >> 2, q = rem & 3;
                src = Bsrc + half * 2048 + r * 16 + q * 4;
                dst = base + (2560 + half * 2560 + r * 20 + q * 4) * 4;
            }
            cp16(dst, src);
        }
        CP_COMMIT();
    };

    load_stage(0, 0);

    int H[4][4], X[4][4];

    for (int j = 0; j < NJ; j++) {
        CP_WAIT0();
        __syncthreads();
        if (j + 1 < NJ) load_stage(j + 1, (j + 1) & 1);

        int kt, g, segw, seg;
        if (j < 2) { kt = j; g = 0; segw = 0; seg = 0; }
        else {
            int p = j - 2;
            int s1 = p / 6, w = (p % 6) >> 1;
            kt = p & 1; g = w; segw = 1 + s1 * 3 + w; seg = 1 + s1;
        }
        if (kt == 0) {
            #pragma unroll
            for (int nt = 0; nt < 4; nt++)
                #pragma unroll
                for (int e = 0; e < 4; e++) { H[nt][e] = 0; X[nt][e] = 0; }
        }

        uint32_t st = sbase + (j & 1) * (STGU * 4);
        unsigned ah[2][4], al[2][4];
        #pragma unroll
        for (int kb2 = 0; kb2 < 2; kb2++) {
            uint32_t ad = st + (uint32_t)(a_base + kb2 * 8) * 4;
            ldsm4(ah[kb2][0], ah[kb2][1], ah[kb2][2], ah[kb2][3], ad);
            ldsm4(al[kb2][0], al[kb2][1], al[kb2][2], al[kb2][3], ad + 1280 * 4);
        }
        #pragma unroll
        for (int kb2 = 0; kb2 < 2; kb2++) {
            #pragma unroll
            for (int p = 0; p < 2; p++) {
                unsigned bh[4], bl[4];
                uint32_t bp = st + (uint32_t)(b_base + p * 320 + kb2 * 8) * 4;
                ldsm4(bh[0], bh[1], bh[2], bh[3], bp);
                ldsm4(bl[0], bl[1], bl[2], bl[3], bp + 2560 * 4);
                #pragma unroll
                for (int q = 0; q < 2; q++) {
                    int nt = 2 * p + q;
                    mma_s8(H[nt], ah[kb2], &bh[2 * q]);
                    mma_s8(X[nt], ah[kb2], &bl[2 * q]);
                    mma_s8(X[nt], al[kb2], &bh[2 * q]);
                }
            }
        }

        if (kt == 1) {
            float sa0 = g_sa[(size_t)seg * NN + ri0];
            float sa1 = g_sa[(size_t)seg * NN + ri1];
            #pragma unroll
            for (int nt = 0; nt < 4; nt++) {
                int col0 = warp_n * 32 + nt * 8 + 2 * lc;
                float s0 = sb_s[segw * 128 + col0];
                float s1v = sb_s[segw * 128 + col0 + 1];
                #pragma unroll
                for (int e = 0; e < 4; e++) {
                    float cs = ((e >> 1) ? sa1 : sa0) * ((e & 1) ? s1v : s0);
                    float tv = 65536.f * (float)H[nt][e] + 256.f * (float)X[nt][e];
                    F[g][nt][e] = fmaf(cs, tv, F[g][nt][e]);
                }
            }
        }
    }

    // ---- epilogue ----
    float dlt = g_delta[0] * (1.f / (float)NN);
    float ampv[2], attv[2];
    #pragma unroll
    for (int rh = 0; rh < 2; rh++) {
        int row = row0 + warp_m * 16 + lr + rh * 8;
        float a = 0.f, b = 0.f;
        if (row < NN) {
            float logd = logf((float)g_deg[row] + 1.f);
            a = logd / dlt;
            b = dlt / fmaxf(logd, 1e-5f);
        }
        ampv[rh] = a;
        attv[rh] = b;
    }
    #pragma unroll
    for (int nt = 0; nt < 4; nt++) {
        int col0 = warp_n * 32 + nt * 8 + 2 * lc;
        float b0 = bias[col0], b1 = bias[col0 + 1];
        #pragma unroll
        for (int rh = 0; rh < 2; rh++) {
            int row = row0 + warp_m * 16 + lr + rh * 8;
            if (row >= NN) continue;
            int e0 = rh * 2;
            float2 v;
            v.x = fmaxf(F[0][nt][e0] + ampv[rh] * F[1][nt][e0]
                        + attv[rh] * F[2][nt][e0] + b0, 0.f);
            v.y = fmaxf(F[0][nt][e0 + 1] + ampv[rh] * F[1][nt][e0 + 1]
                        + attv[rh] * F[2][nt][e0 + 1] + b1, 0.f);
            *(float2*)&hout[(size_t)row * DH + col0] = v;
        }
    }
}

// ---------------- pooling + bn/fc --------------------------------------------
#define POOL_NB 256
__global__ __launch_bounds__(128) void pool_kernel(
        const float* __restrict__ h, const int* __restrict__ batch) {
    int n0 = blockIdx.x * POOL_NB;
    int t = threadIdx.x;
    int nend = min(n0 + POOL_NB, NN);
    int cnt = nend - n0;
    __shared__ int sbm[POOL_NB];
    for (int i = t; i < cnt; i += 128) sbm[i] = batch[n0 + i];
    __syncthreads();
    float acc = 0.f;
    int cur = sbm[0];
    for (int i = 0; i < cnt; i++) {
        int b = sbm[i];
        if (b != cur) {
            atomicAdd(&g_pool[cur * DH + t], acc);
            acc = 0.f; cur = b;
        }
        acc += h[(size_t)(n0 + i) * DH + t];
    }
    atomicAdd(&g_pool[cur * DH + t], acc);
}

__global__ __launch_bounds__(128) void bnfc_kernel(
        const float* __restrict__ gamma, const float* __restrict__ beta,
        const float* __restrict__ fcW, const float* __restrict__ fcb,
        float* __restrict__ out) {
    __shared__ float sp[NG * DH];
    int t = threadIdx.x;
    for (int i = t; i < NG * DH; i += 128) sp[i] = g_pool[i];
    __syncthreads();
    float m = 0.f;
    #pragma unroll 4
    for (int g = 0; g < NG; g++) m += sp[g * DH + t];
    m *= (1.f / NG);
    float v = 0.f;
    #pragma unroll 4
    for (int g = 0; g < NG; g++) { float d = sp[g * DH + t] - m; v += d * d; }
    v *= (1.f / NG);
    float rs = rsqrtf(v + 1e-5f);
    float ga = gamma[t], be = beta[t];
    for (int g = 0; g < NG; g++)
        sp[g * DH + t] = (sp[g * DH + t] - m) * rs * ga + be;
    __syncthreads();
    for (int i = t; i < NG * DLAT; i += 128) {
        int g = i / DLAT, jj = i % DLAT;
        float s = fcb[jj];
        #pragma unroll 8
        for (int c = 0; c < DH; c++) s += sp[g * DH + c] * fcW[c * DLAT + jj];
        out[i] = s;
    }
}

// ---------------- launch ------------------------------------------------------
extern "C" void kernel_launch(void* const* d_in, const int* in_sizes, int n_in,
                              void* d_out, int out_size) {
    const float* x     = (const float*)d_in[0];
    const int*   ei    = (const int*)d_in[1];
    const int*   batch = (const int*)d_in[2];
    const float* W0 = (const float*)d_in[3];  const float* b0 = (const float*)d_in[4];
    const float* W1 = (const float*)d_in[5];  const float* b1 = (const float*)d_in[6];
    const float* W2 = (const float*)d_in[7];  const float* b2 = (const float*)d_in[8];
    const float* gamma = (const float*)d_in[9];
    const float* beta  = (const float*)d_in[10];
    const float* fcW   = (const float*)d_in[11];
    const float* fcb   = (const float*)d_in[12];
    float* out = (float*)d_out;

    void *p_deg, *p_cur, *p_delta, *p_pool, *p_h0, *p_h1, *p_w, *p_sb;
    cudaGetSymbolAddress(&p_deg,   g_deg);
    cudaGetSymbolAddress(&p_cur,   g_cur);
    cudaGetSymbolAddress(&p_delta, g_delta);
    cudaGetSymbolAddress(&p_pool,  g_pool);
    cudaGetSymbolAddress(&p_h0,    g_h0);
    cudaGetSymbolAddress(&p_h1,    g_h1);
    cudaGetSymbolAddress(&p_w,     g_W);
    cudaGetSymbolAddress(&p_sb,    g_sb);
    float* h0 = (float*)p_h0;
    float* h1 = (float*)p_h1;
    unsigned* wimg = (unsigned*)p_w;
    float* sb = (float*)p_sb;

    cudaFuncSetAttribute(gemm_i8_kernel,
                         cudaFuncAttributeMaxDynamicSharedMemorySize, SMEM_BYTES);

    cudaMemsetAsync(p_deg,   0, NN * sizeof(int));
    cudaMemsetAsync(p_cur,   0, NN * sizeof(int));
    cudaMemsetAsync(p_delta, 0, sizeof(float));
    cudaMemsetAsync(p_pool,  0, NG * DH * sizeof(float));

    const float* Ws[3] = {W0, W1, W2};
    for (int l = 0; l < 3; l++) {
        wscale_kernel<<<13, 128>>>(Ws[l], sb + l * 13 * 128);
        wquant_kernel<<<(NJ * 2048 + 255) / 256, 256>>>(Ws[l], sb + l * 13 * 128,
                                                        wimg + (size_t)l * WL);
    }

    int eblocks = (NE + 1023) / 1024;
    int sblocks = (NN + 1023) / 1024;
    hist_kernel<<<eblocks, 1024>>>(ei);
    scan1_kernel<<<sblocks, 1024>>>();
    scan2_kernel<<<1, 32>>>(sblocks);
    scan3_kernel<<<sblocks, 1024>>>();
    scatter_kernel<<<eblocks, 1024>>>(ei);
    delta_kernel<<<128, 256>>>();

    int gblocks = (NN + 63) / 64;   // 782

    // layer 0
    hquant_kernel<<<NN, 128>>>(x);
    agg_kernel<<<NN, 128>>>(x);
    gemm_i8_kernel<<<gblocks, 512, SMEM_BYTES>>>(wimg, sb, b0, h0);
    // layer 1
    hquant_kernel<<<NN, 128>>>(h0);
    agg_kernel<<<NN, 128>>>(h0);
    gemm_i8_kernel<<<gblocks, 512, SMEM_BYTES>>>(wimg + WL, sb + 13 * 128, b1, h1);
    // layer 2
    hquant_kernel<<<NN, 128>>>(h1);
    agg_kernel<<<NN, 128>>>(h1);
    gemm_i8_kernel<<<gblocks, 512, SMEM_BYTES>>>(wimg + 2 * (size_t)WL,
                                                 sb + 2 * 13 * 128, b2, h0);

    pool_kernel<<<(NN + POOL_NB - 1) / POOL_NB, 128>>>(h0, batch);
    bnfc_kernel<<<1, 128>>>(gamma, beta, fcW, fcb, out);
}

// round 11
// speedup vs baseline: 2.9472x; 2.9241x over previous
#include <cuda_runtime.h>
#include <cuda_bf16.h>
#include <math.h>
#include <stdint.h>

// Problem constants (fixed by the reference)
#define NN 50000
#define NE 600000
#define NG 64
#define DH 128
#define DLAT 64
#define MAXD 128          // degree buckets (max deg ~40 for this graph)
#define NJ 20             // GEMM jobs: 4 h (k32) + 16 agg (k32); K=640
#define MAXB 1024         // fixed GEMM grid
#define STGU 7680         // u32 per smem stage
#define SMEM_BYTES (2 * STGU * 4)

// ---------------- device scratch ------------------------------------------
__device__ int   g_deg[NN];
__device__ int   g_off[NN + 1];
__device__ int   g_cur[NN];
__device__ int   g_csr[NE];
__device__ int   g_bsum[64];
__device__ float g_delta[1];
__device__ float g_h0[(size_t)NN * DH];
__device__ float g_h1[(size_t)NN * DH];
__device__ unsigned g_Hh[(size_t)NN * 64];    // slot-permuted h image hi
__device__ unsigned g_Hl[(size_t)NN * 64];
__device__ unsigned g_Agh[(size_t)NN * 256];  // slot-permuted agg image hi
__device__ unsigned g_Agl[(size_t)NN * 256];
__device__ unsigned g_WhImg[3 * 4 * 4096];    // per-layer Wh jobs
__device__ unsigned g_WcImg[(size_t)3 * MAXD * 16 * 4096]; // per (layer,deg) Wc jobs
__device__ int   g_dcnt[MAXD];
__device__ int   g_dstart[MAXD];
__device__ int   g_dcur[MAXD];
__device__ int   g_rank[NN];      // node -> slot
__device__ int   g_s2n[NN];       // slot -> node
__device__ int   g_blk_deg[MAXB];
__device__ int   g_blk_row0[MAXB];
__device__ int   g_blk_end[MAXB];
__device__ int   g_nblk[1];
__device__ float g_pool[NG * DH];

// ---------------- helpers --------------------------------------------------
__device__ __forceinline__ void split_pair(float f0, float f1,
                                           unsigned& hi, unsigned& lo) {
    __nv_bfloat16 h0 = __float2bfloat16_rn(f0);
    __nv_bfloat16 h1 = __float2bfloat16_rn(f1);
    float r0 = f0 - __bfloat162float(h0);
    float r1 = f1 - __bfloat162float(h1);
    __nv_bfloat162 H; H.x = h0; H.y = h1;
    __nv_bfloat162 L = __floats2bfloat162_rn(r0, r1);
    hi = *reinterpret_cast<unsigned*>(&H);
    lo = *reinterpret_cast<unsigned*>(&L);
}
__device__ __forceinline__ void mma_bf16(float* d, const unsigned* a,
                                         const unsigned* b) {
    asm volatile(
        "mma.sync.aligned.m16n8k16.row.col.f32.bf16.bf16.f32 "
        "{%0,%1,%2,%3}, {%4,%5,%6,%7}, {%8,%9}, {%0,%1,%2,%3};\n"
        : "+f"(d[0]), "+f"(d[1]), "+f"(d[2]), "+f"(d[3])
        : "r"(a[0]), "r"(a[1]), "r"(a[2]), "r"(a[3]), "r"(b[0]), "r"(b[1]));
}
__device__ __forceinline__ void ldsm4(unsigned& r0, unsigned& r1,
                                      unsigned& r2, unsigned& r3, uint32_t a) {
    asm volatile("ldmatrix.sync.aligned.m8n8.x4.shared.b16 {%0,%1,%2,%3}, [%4];"
                 : "=r"(r0), "=r"(r1), "=r"(r2), "=r"(r3) : "r"(a));
}
__device__ __forceinline__ uint32_t smem_u32(const void* p) {
    uint32_t a;
    asm("{ .reg .u64 t; cvta.to.shared.u64 t, %1; cvt.u32.u64 %0, t; }"
        : "=r"(a) : "l"(p));
    return a;
}
__device__ __forceinline__ void cp16(uint32_t dst, const void* src) {
    asm volatile("cp.async.cg.shared.global [%0], [%1], 16;"
                 :: "r"(dst), "l"(src));
}
#define CP_COMMIT() asm volatile("cp.async.commit_group;" ::: "memory")
#define CP_WAIT0()  asm volatile("cp.async.wait_group 0;" ::: "memory")

// ---------------- graph prep ----------------------------------------------
__global__ void hist_kernel(const int* __restrict__ ei) {
    int e = blockIdx.x * blockDim.x + threadIdx.x;
    int stride = gridDim.x * blockDim.x;
    for (; e < NE; e += stride) atomicAdd(&g_deg[ei[NE + e]], 1);
}
__global__ void scan1_kernel() {
    __shared__ int sh[1024];
    int b = blockIdx.x, t = threadIdx.x;
    int i = b * 1024 + t;
    int v = (i < NN) ? g_deg[i] : 0;
    sh[t] = v;
    __syncthreads();
    #pragma unroll
    for (int s = 1; s < 1024; s <<= 1) {
        int add = (t >= s) ? sh[t - s] : 0;
        __syncthreads();
        sh[t] += add;
        __syncthreads();
    }
    if (i < NN) g_off[i] = sh[t] - v;
    if (t == 1023) g_bsum[b] = sh[1023];
}
__global__ void scan2_kernel(int nblk) {
    if (threadIdx.x == 0) {
        int c = 0;
        for (int b = 0; b < nblk; b++) { int s = g_bsum[b]; g_bsum[b] = c; c += s; }
        g_off[NN] = c;
    }
}
__global__ void scan3_kernel() {
    int i = blockIdx.x * 1024 + threadIdx.x;
    if (i < NN) g_off[i] += g_bsum[blockIdx.x];
}
__global__ void scatter_kernel(const int* __restrict__ ei) {
    int e = blockIdx.x * blockDim.x + threadIdx.x;
    int stride = gridDim.x * blockDim.x;
    for (; e < NE; e += stride) {
        int dst = ei[NE + e];
        int pos = g_off[dst] + atomicAdd(&g_cur[dst], 1);
        g_csr[pos] = ei[e];
    }
}
__global__ void delta_kernel() {
    int i = blockIdx.x * blockDim.x + threadIdx.x;
    int stride = gridDim.x * blockDim.x;
    float s = 0.f;
    for (; i < NN; i += stride) s += logf((float)g_deg[i] + 1.f);
    #pragma unroll
    for (int o = 16; o > 0; o >>= 1) s += __shfl_down_sync(0xffffffffu, s, o);
    __shared__ float sh[32];
    int lane = threadIdx.x & 31, wid = threadIdx.x >> 5;
    if (lane == 0) sh[wid] = s;
    __syncthreads();
    if (wid == 0) {
        float v = (lane < (int)(blockDim.x >> 5)) ? sh[lane] : 0.f;
        #pragma unroll
        for (int o = 16; o > 0; o >>= 1) v += __shfl_down_sync(0xffffffffu, v, o);
        if (lane == 0) atomicAdd(&g_delta[0], v);
    }
}

// ---------------- degree bucketing ------------------------------------------
__global__ void dhist_kernel() {
    int n = blockIdx.x * blockDim.x + threadIdx.x;
    if (n < NN) atomicAdd(&g_dcnt[min(g_deg[n], MAXD - 1)], 1);
}
__global__ void dscan_kernel() {
    if (threadIdx.x == 0) {
        int c = 0;
        for (int d = 0; d < MAXD; d++) { g_dstart[d] = c; c += g_dcnt[d]; }
    }
}
__global__ void rank_kernel() {
    int n = blockIdx.x * blockDim.x + threadIdx.x;
    if (n >= NN) return;
    int d = min(g_deg[n], MAXD - 1);
    int pos = g_dstart[d] + atomicAdd(&g_dcur[d], 1);
    g_rank[n] = pos;
    g_s2n[pos] = n;
}
__global__ void blkmap_kernel() {
    if (threadIdx.x == 0) {
        int nb = 0;
        for (int d = 0; d < MAXD; d++) {
            int c = g_dcnt[d], s = g_dstart[d];
            for (int r = 0; r < c; r += 64) {
                g_blk_deg[nb] = d;
                g_blk_row0[nb] = s + r;
                g_blk_end[nb] = s + c;
                nb++;
            }
        }
        g_nblk[0] = nb;
    }
}

// ---------------- W images ----------------------------------------------------
// Wh: rows 0..127 of W -> 4 jobs (k32), buffer [n=128][c=16] u32 hi, lo@+2048.
__global__ void whsplit_kernel(const float* __restrict__ W,
                               unsigned* __restrict__ img) {
    int i = blockIdx.x * blockDim.x + threadIdx.x;
    if (i >= 4 * 2048) return;
    int j = i >> 11, rem = i & 2047;
    int n = rem >> 4, c = rem & 15;
    int kg = j * 32 + 2 * c;
    unsigned hi, lo;
    split_pair(W[(size_t)kg * DH + n], W[(size_t)(kg + 1) * DH + n], hi, lo);
    img[(size_t)j * 4096 + n * 16 + c] = hi;
    img[(size_t)j * 4096 + 2048 + n * 16 + c] = lo;
}

// Wc(d) = W1 + amp(d) W2 + att(d) W3 (512x128) -> 16 jobs per degree.
__global__ void wcomb_kernel(const float* __restrict__ W,
                             unsigned* __restrict__ img) {
    int d = blockIdx.x;
    if (g_dcnt[d] == 0) return;
    float dlt = g_delta[0] * (1.f / (float)NN);
    float logd = logf((float)d + 1.f);
    float amp = logd / dlt;
    float att = dlt / fmaxf(logd, 1e-5f);
    unsigned* dst = img + (size_t)d * 16 * 4096;
    for (int idx = blockIdx.y * 256 + threadIdx.x; idx < 32768; idx += 32 * 256) {
        int j = idx >> 11;
        int rem = idx & 2047;
        int n = rem >> 4, c = rem & 15;
        int kg = j * 32 + 2 * c;
        float v0 = W[(size_t)(128 + kg) * DH + n]
                 + amp * W[(size_t)(640 + kg) * DH + n]
                 + att * W[(size_t)(1152 + kg) * DH + n];
        float v1 = W[(size_t)(129 + kg) * DH + n]
                 + amp * W[(size_t)(641 + kg) * DH + n]
                 + att * W[(size_t)(1153 + kg) * DH + n];
        unsigned hi, lo;
        split_pair(v0, v1, hi, lo);
        dst[(size_t)j * 4096 + n * 16 + c] = hi;
        dst[(size_t)j * 4096 + 2048 + n * 16 + c] = lo;
    }
}

// ---------------- x / h split (slot-permuted) -------------------------------
__global__ void xsplit_kernel(const float* __restrict__ x) {
    int i = blockIdx.x * blockDim.x + threadIdx.x;
    if (i >= NN * 64) return;
    int n = i >> 6, p = i & 63;
    int slot = g_rank[n];
    unsigned hi, lo;
    split_pair(x[(size_t)n * DH + 2 * p], x[(size_t)n * DH + 2 * p + 1], hi, lo);
    g_Hh[(size_t)slot * 64 + p] = hi;
    g_Hl[(size_t)slot * 64 + p] = lo;
}

// ---------------- aggregation -> slot-permuted split agg image ---------------
__global__ __launch_bounds__(128) void agg_kernel(const float* __restrict__ h) {
    int n = blockIdx.x;
    int t = threadIdx.x;
    int beg = g_off[n], end = g_off[n + 1];
    int d = end - beg;
    float s = 0.f, ss = 0.f;
    float mx = __int_as_float(0xff800000);
    float mn = __int_as_float(0x7f800000);
    __shared__ int ssrc[128];
    for (int base = beg; base < end; base += 128) {
        int cnt = min(128, end - base);
        if (t < cnt) ssrc[t] = g_csr[base + t];
        __syncthreads();
        #pragma unroll 4
        for (int i = 0; i < cnt; i++) {
            float m = h[(size_t)ssrc[i] * DH + t];
            s += m; ss += m * m;
            mx = fmaxf(mx, m); mn = fminf(mn, m);
        }
        __syncthreads();
    }
    float cntf = fmaxf((float)d, 1.f);
    float mean = s / cntf;
    float var = fmaxf(ss / cntf - mean * mean, 0.f);
    float stdv = sqrtf(var + 1e-5f);
    if (d == 0) { mx = 0.f; mn = 0.f; }

    __shared__ float sf[512];
    sf[t] = mean;
    sf[128 + t] = mx;
    sf[256 + t] = mn;
    sf[384 + t] = stdv;
    __syncthreads();

    size_t rowb = (size_t)g_rank[n] * 256;
    #pragma unroll
    for (int p = t; p < 256; p += 128) {
        unsigned hi, lo;
        split_pair(sf[2 * p], sf[2 * p + 1], hi, lo);
        g_Agh[rowb + p] = hi;
        g_Agl[rowb + p] = lo;
    }
}

// ---------------- bf16x3 GEMM, degree-bucketed -------------------------------
// block = 64 rows (one degree) x 128 cols; 256 threads (8 warps 2m x 4n).
// stage (u32): A hi[64][20]@0 lo@1280; B hi[128][20]@2560 lo@5120.
__global__ __launch_bounds__(256, 2) void gemm_deg_kernel(
        const unsigned* __restrict__ WhImg, const unsigned* __restrict__ WcImg,
        const float* __restrict__ bias, float* __restrict__ hout,
        int write_split) {
    int b = blockIdx.x;
    if (b >= g_nblk[0]) return;
    extern __shared__ unsigned smem_u[];
    const uint32_t sbase = smem_u32(smem_u);

    const int row0 = g_blk_row0[b];
    const int blkend = g_blk_end[b];
    const unsigned* Wc = WcImg + (size_t)g_blk_deg[b] * 16 * 4096;

    const int tid = threadIdx.x;
    const int lane = tid & 31, wid = tid >> 5;
    const int warp_m = wid >> 2;   // 0..1 (32 rows)
    const int warp_n = wid & 3;    // 0..3 (32 cols)
    const int lr = lane >> 2, lc = lane & 3;
    const int lg = lane >> 3, l8 = lane & 7;
    const int a_row = ((lg & 1) << 3) + l8;
    const int a_col = (lg >> 1) << 2;
    const int b_row = ((lg >> 1) << 3) + l8;
    const int b_col = (lg & 1) << 2;
    const int a_base = (warp_m * 32 + a_row) * 20 + a_col;     // + mt*320 + kb
    const int b_base = 2560 + (warp_n * 32 + b_row) * 20 + b_col; // + p*320 + kb

    float acc[2][4][4];
    #pragma unroll
    for (int mt = 0; mt < 2; mt++)
        #pragma unroll
        for (int nt = 0; nt < 4; nt++)
            #pragma unroll
            for (int e = 0; e < 4; e++) acc[mt][nt][e] = 0.f;

    auto load_stage = [&](int j, int slot) {
        uint32_t base = sbase + slot * (STGU * 4);
        const unsigned *Ah, *Al, *Bsrc;
        int K2, coff;
        if (j < 4) {
            Ah = g_Hh; Al = g_Hl; K2 = 64; coff = j * 16;
            Bsrc = WhImg + (size_t)j * 4096;
        } else {
            Ah = g_Agh; Al = g_Agl; K2 = 256; coff = (j - 4) * 16;
            Bsrc = Wc + (size_t)(j - 4) * 4096;
        }
        #pragma unroll
        for (int c0 = 0; c0 < 6; c0++) {
            int c = c0 * 256 + tid;
            uint32_t dst;
            const unsigned* src;
            if (c < 512) {
                int half = (c >= 256) ? 1 : 0;
                int rem = c - half * 256;
                int r = rem >> 2, q = rem & 3;
                int slotr = min(row0 + r, blkend - 1);
                src = (half ? Al : Ah) + (size_t)slotr * K2 + coff + q * 4;
                dst = base + (half * 1280 + r * 20 + q * 4) * 4;
            } else {
                int cb = c - 512;
                int half = cb >> 9;
                int rem = cb & 511;
                int r = rem >> 2, q = rem & 3;
                src = Bsrc + half * 2048 + r * 16 + q * 4;
                dst = base + (2560 + half * 2560 + r * 20 + q * 4) * 4;
            }
            cp16(dst, src);
        }
        CP_COMMIT();
    };

    load_stage(0, 0);

    for (int j = 0; j < NJ; j++) {
        CP_WAIT0();
        __syncthreads();
        if (j + 1 < NJ) load_stage(j + 1, (j + 1) & 1);

        uint32_t st = sbase + (j & 1) * (STGU * 4);
        #pragma unroll
        for (int kb = 0; kb < 16; kb += 8) {
            unsigned ah[2][4], al[2][4];
            #pragma unroll
            for (int mt = 0; mt < 2; mt++) {
                uint32_t ad = st + (uint32_t)(a_base + mt * 320 + kb) * 4;
                ldsm4(ah[mt][0], ah[mt][1], ah[mt][2], ah[mt][3], ad);
                ldsm4(al[mt][0], al[mt][1], al[mt][2], al[mt][3], ad + 1280 * 4);
            }
            #pragma unroll
            for (int p = 0; p < 2; p++) {
                unsigned bh[4], bl[4];
                uint32_t bp = st + (uint32_t)(b_base + p * 320 + kb) * 4;
                ldsm4(bh[0], bh[1], bh[2], bh[3], bp);
                ldsm4(bl[0], bl[1], bl[2], bl[3], bp + 2560 * 4);
                #pragma unroll
                for (int q = 0; q < 2; q++) {
                    int nt = 2 * p + q;
                    #pragma unroll
                    for (int mt = 0; mt < 2; mt++) {
                        mma_bf16(acc[mt][nt], ah[mt], &bh[2 * q]);
                        mma_bf16(acc[mt][nt], al[mt], &bh[2 * q]);
                        mma_bf16(acc[mt][nt], ah[mt], &bl[2 * q]);
                    }
                }
            }
        }
    }

    // ---- epilogue: bias + relu, scatter to node order, optional h-image -----
    #pragma unroll
    for (int mt = 0; mt < 2; mt++)
        #pragma unroll
        for (int nt = 0; nt < 4; nt++) {
            int col0 = warp_n * 32 + nt * 8 + 2 * lc;
            float b0 = bias[col0], b1 = bias[col0 + 1];
            #pragma unroll
            for (int rh = 0; rh < 2; rh++) {
                int slot = row0 + warp_m * 32 + mt * 16 + lr + rh * 8;
                if (slot >= blkend) continue;
                int node = g_s2n[slot];
                int e0 = rh * 2;
                float2 v;
                v.x = fmaxf(acc[mt][nt][e0] + b0, 0.f);
                v.y = fmaxf(acc[mt][nt][e0 + 1] + b1, 0.f);
                *(float2*)&hout[(size_t)node * DH + col0] = v;
                if (write_split) {
                    unsigned hi, lo;
                    split_pair(v.x, v.y, hi, lo);
                    g_Hh[(size_t)slot * 64 + (col0 >> 1)] = hi;
                    g_Hl[(size_t)slot * 64 + (col0 >> 1)] = lo;
                }
            }
        }
}

// ---------------- pooling + bn/fc --------------------------------------------
#define POOL_NB 256
__global__ __launch_bounds__(128) void pool_kernel(
        const float* __restrict__ h, const int* __restrict__ batch) {
    int n0 = blockIdx.x * POOL_NB;
    int t = threadIdx.x;
    int nend = min(n0 + POOL_NB, NN);
    int cnt = nend - n0;
    __shared__ int sbm[POOL_NB];
    for (int i = t; i < cnt; i += 128) sbm[i] = batch[n0 + i];
    __syncthreads();
    float acc = 0.f;
    int cur = sbm[0];
    for (int i = 0; i < cnt; i++) {
        int b = sbm[i];
        if (b != cur) {
            atomicAdd(&g_pool[cur * DH + t], acc);
            acc = 0.f; cur = b;
        }
        acc += h[(size_t)(n0 + i) * DH + t];
    }
    atomicAdd(&g_pool[cur * DH + t], acc);
}

__global__ __launch_bounds__(128) void bnfc_kernel(
        const float* __restrict__ gamma, const float* __restrict__ beta,
        const float* __restrict__ fcW, const float* __restrict__ fcb,
        float* __restrict__ out) {
    __shared__ float sp[NG * DH];
    int t = threadIdx.x;
    for (int i = t; i < NG * DH; i += 128) sp[i] = g_pool[i];
    __syncthreads();
    float m = 0.f;
    #pragma unroll 4
    for (int g = 0; g < NG; g++) m += sp[g * DH + t];
    m *= (1.f / NG);
    float v = 0.f;
    #pragma unroll 4
    for (int g = 0; g < NG; g++) { float d = sp[g * DH + t] - m; v += d * d; }
    v *= (1.f / NG);
    float rs = rsqrtf(v + 1e-5f);
    float ga = gamma[t], be = beta[t];
    for (int g = 0; g < NG; g++)
        sp[g * DH + t] = (sp[g * DH + t] - m) * rs * ga + be;
    __syncthreads();
    for (int i = t; i < NG * DLAT; i += 128) {
        int g = i / DLAT, jj = i % DLAT;
        float s = fcb[jj];
        #pragma unroll 8
        for (int c = 0; c < DH; c++) s += sp[g * DH + c] * fcW[c * DLAT + jj];
        out[i] = s;
    }
}

// ---------------- launch ------------------------------------------------------
extern "C" void kernel_launch(void* const* d_in, const int* in_sizes, int n_in,
                              void* d_out, int out_size) {
    const float* x     = (const float*)d_in[0];
    const int*   ei    = (const int*)d_in[1];
    const int*   batch = (const int*)d_in[2];
    const float* W0 = (const float*)d_in[3];  const float* b0 = (const float*)d_in[4];
    const float* W1 = (const float*)d_in[5];  const float* b1 = (const float*)d_in[6];
    const float* W2 = (const float*)d_in[7];  const float* b2 = (const float*)d_in[8];
    const float* gamma = (const float*)d_in[9];
    const float* beta  = (const float*)d_in[10];
    const float* fcW   = (const float*)d_in[11];
    const float* fcb   = (const float*)d_in[12];
    float* out = (float*)d_out;

    void *p_deg, *p_cur, *p_delta, *p_pool, *p_h0, *p_h1;
    void *p_wh, *p_wc, *p_dcnt, *p_dcur;
    cudaGetSymbolAddress(&p_deg,   g_deg);
    cudaGetSymbolAddress(&p_cur,   g_cur);
    cudaGetSymbolAddress(&p_delta, g_delta);
    cudaGetSymbolAddress(&p_pool,  g_pool);
    cudaGetSymbolAddress(&p_h0,    g_h0);
    cudaGetSymbolAddress(&p_h1,    g_h1);
    cudaGetSymbolAddress(&p_wh,    g_WhImg);
    cudaGetSymbolAddress(&p_wc,    g_WcImg);
    cudaGetSymbolAddress(&p_dcnt,  g_dcnt);
    cudaGetSymbolAddress(&p_dcur,  g_dcur);
    float* h0 = (float*)p_h0;
    float* h1 = (float*)p_h1;
    unsigned* whimg = (unsigned*)p_wh;
    unsigned* wcimg = (unsigned*)p_wc;

    cudaFuncSetAttribute(gemm_deg_kernel,
                         cudaFuncAttributeMaxDynamicSharedMemorySize, SMEM_BYTES);

    cudaMemsetAsync(p_deg,   0, NN * sizeof(int));
    cudaMemsetAsync(p_cur,   0, NN * sizeof(int));
    cudaMemsetAsync(p_delta, 0, sizeof(float));
    cudaMemsetAsync(p_pool,  0, NG * DH * sizeof(float));
    cudaMemsetAsync(p_dcnt,  0, MAXD * sizeof(int));
    cudaMemsetAsync(p_dcur,  0, MAXD * sizeof(int));

    int eblocks = (NE + 1023) / 1024;
    int sblocks = (NN + 1023) / 1024;
    hist_kernel<<<eblocks, 1024>>>(ei);
    scan1_kernel<<<sblocks, 1024>>>();
    scan2_kernel<<<1, 32>>>(sblocks);
    scan3_kernel<<<sblocks, 1024>>>();
    scatter_kernel<<<eblocks, 1024>>>(ei);
    delta_kernel<<<128, 256>>>();

    // degree bucketing
    dhist_kernel<<<(NN + 255) / 256, 256>>>();
    dscan_kernel<<<1, 32>>>();
    rank_kernel<<<(NN + 255) / 256, 256>>>();
    blkmap_kernel<<<1, 32>>>();

    // W images (wcomb needs delta)
    const size_t WHL = 4 * 4096;
    const size_t WCL = (size_t)MAXD * 16 * 4096;
    whsplit_kernel<<<(4 * 2048 + 255) / 256, 256>>>(W0, whimg);
    whsplit_kernel<<<(4 * 2048 + 255) / 256, 256>>>(W1, whimg + WHL);
    whsplit_kernel<<<(4 * 2048 + 255) / 256, 256>>>(W2, whimg + 2 * WHL);
    wcomb_kernel<<<dim3(MAXD, 32), 256>>>(W0, wcimg);
    wcomb_kernel<<<dim3(MAXD, 32), 256>>>(W1, wcimg + WCL);
    wcomb_kernel<<<dim3(MAXD, 32), 256>>>(W2, wcimg + 2 * WCL);

    xsplit_kernel<<<(NN * 64 + 255) / 256, 256>>>(x);

    // layer 0
    agg_kernel<<<NN, 128>>>(x);
    gemm_deg_kernel<<<MAXB, 256, SMEM_BYTES>>>(whimg, wcimg, b0, h0, 1);
    // layer 1
    agg_kernel<<<NN, 128>>>(h0);
    gemm_deg_kernel<<<MAXB, 256, SMEM_BYTES>>>(whimg + WHL, wcimg + WCL, b1, h1, 1);
    // layer 2
    agg_kernel<<<NN, 128>>>(h1);
    gemm_deg_kernel<<<MAXB, 256, SMEM_BYTES>>>(whimg + 2 * WHL, wcimg + 2 * WCL,
                                               b2, h0, 0);

    pool_kernel<<<(NN + POOL_NB - 1) / POOL_NB, 128>>>(h0, batch);
    bnfc_kernel<<<1, 128>>>(gamma, beta, fcW, fcb, out);
}

// round 12
// speedup vs baseline: 3.3278x; 1.1291x over previous
#include <cuda_runtime.h>
#include <cuda_bf16.h>
#include <math.h>
#include <stdint.h>

// Problem constants (fixed by the reference)
#define NN 50000
#define NE 600000
#define NG 64
#define DH 128
#define DLAT 64
#define MAXD 128          // degree buckets (max deg ~40 for this graph)
#define NJ 20             // GEMM jobs: 4 h (k32) + 16 agg (k32); K=640
#define MAXB 1024         // fixed GEMM grid
#define STGU 7680         // u32 per smem stage
#define SMEM_BYTES (2 * STGU * 4)

// ---------------- device scratch ------------------------------------------
__device__ int   g_deg[NN];
__device__ int   g_off[NN + 1];
__device__ int   g_cur[NN];
__device__ int   g_csr[NE];
__device__ int   g_bsum[64];
__device__ float g_delta[1];
__device__ float g_h0[(size_t)NN * DH];
__device__ float g_h1[(size_t)NN * DH];
__device__ unsigned g_Hh[(size_t)NN * 64];    // slot-permuted h image hi
__device__ unsigned g_Hl[(size_t)NN * 64];
__device__ unsigned g_Agh[(size_t)NN * 256];  // slot-permuted agg image hi
__device__ unsigned g_Agl[(size_t)NN * 256];
__device__ unsigned g_WhImg[3 * 4 * 4096];    // per-layer Wh jobs
__device__ unsigned g_WcImg[(size_t)3 * MAXD * 16 * 4096]; // per (layer,deg) Wc jobs
__device__ int   g_dcnt[MAXD];
__device__ int   g_dstart[MAXD];
__device__ int   g_dcur[MAXD];
__device__ int   g_rank[NN];      // node -> slot
__device__ int   g_s2n[NN];       // slot -> node
__device__ int   g_blk_deg[MAXB];
__device__ int   g_blk_row0[MAXB];
__device__ int   g_blk_end[MAXB];
__device__ int   g_nblk[1];
__device__ float g_pool[NG * DH];

// ---------------- helpers --------------------------------------------------
__device__ __forceinline__ void split_pair(float f0, float f1,
                                           unsigned& hi, unsigned& lo) {
    __nv_bfloat16 h0 = __float2bfloat16_rn(f0);
    __nv_bfloat16 h1 = __float2bfloat16_rn(f1);
    float r0 = f0 - __bfloat162float(h0);
    float r1 = f1 - __bfloat162float(h1);
    __nv_bfloat162 H; H.x = h0; H.y = h1;
    __nv_bfloat162 L = __floats2bfloat162_rn(r0, r1);
    hi = *reinterpret_cast<unsigned*>(&H);
    lo = *reinterpret_cast<unsigned*>(&L);
}
__device__ __forceinline__ void mma_bf16(float* d, const unsigned* a,
                                         const unsigned* b) {
    asm volatile(
        "mma.sync.aligned.m16n8k16.row.col.f32.bf16.bf16.f32 "
        "{%0,%1,%2,%3}, {%4,%5,%6,%7}, {%8,%9}, {%0,%1,%2,%3};\n"
        : "+f"(d[0]), "+f"(d[1]), "+f"(d[2]), "+f"(d[3])
        : "r"(a[0]), "r"(a[1]), "r"(a[2]), "r"(a[3]), "r"(b[0]), "r"(b[1]));
}
__device__ __forceinline__ void ldsm4(unsigned& r0, unsigned& r1,
                                      unsigned& r2, unsigned& r3, uint32_t a) {
    asm volatile("ldmatrix.sync.aligned.m8n8.x4.shared.b16 {%0,%1,%2,%3}, [%4];"
                 : "=r"(r0), "=r"(r1), "=r"(r2), "=r"(r3) : "r"(a));
}
__device__ __forceinline__ uint32_t smem_u32(const void* p) {
    uint32_t a;
    asm("{ .reg .u64 t; cvta.to.shared.u64 t, %1; cvt.u32.u64 %0, t; }"
        : "=r"(a) : "l"(p));
    return a;
}
__device__ __forceinline__ void cp16(uint32_t dst, const void* src) {
    asm volatile("cp.async.cg.shared.global [%0], [%1], 16;"
                 :: "r"(dst), "l"(src));
}
#define CP_COMMIT() asm volatile("cp.async.commit_group;" ::: "memory")
#define CP_WAIT0()  asm volatile("cp.async.wait_group 0;" ::: "memory")

// ---------------- graph prep ----------------------------------------------
__global__ void hist_kernel(const int* __restrict__ ei) {
    int e = blockIdx.x * blockDim.x + threadIdx.x;
    int stride = gridDim.x * blockDim.x;
    for (; e < NE; e += stride) atomicAdd(&g_deg[ei[NE + e]], 1);
}
__global__ void scan1_kernel() {
    __shared__ int sh[1024];
    int b = blockIdx.x, t = threadIdx.x;
    int i = b * 1024 + t;
    int v = (i < NN) ? g_deg[i] : 0;
    sh[t] = v;
    __syncthreads();
    #pragma unroll
    for (int s = 1; s < 1024; s <<= 1) {
        int add = (t >= s) ? sh[t - s] : 0;
        __syncthreads();
        sh[t] += add;
        __syncthreads();
    }
    if (i < NN) g_off[i] = sh[t] - v;
    if (t == 1023) g_bsum[b] = sh[1023];
}
__global__ void scan2_kernel(int nblk) {
    if (threadIdx.x == 0) {
        int c = 0;
        for (int b = 0; b < nblk; b++) { int s = g_bsum[b]; g_bsum[b] = c; c += s; }
        g_off[NN] = c;
    }
}
__global__ void scan3_kernel() {
    int i = blockIdx.x * 1024 + threadIdx.x;
    if (i < NN) g_off[i] += g_bsum[blockIdx.x];
}
__global__ void scatter_kernel(const int* __restrict__ ei) {
    int e = blockIdx.x * blockDim.x + threadIdx.x;
    int stride = gridDim.x * blockDim.x;
    for (; e < NE; e += stride) {
        int dst = ei[NE + e];
        int pos = g_off[dst] + atomicAdd(&g_cur[dst], 1);
        g_csr[pos] = ei[e];
    }
}
__global__ void delta_kernel() {
    int i = blockIdx.x * blockDim.x + threadIdx.x;
    int stride = gridDim.x * blockDim.x;
    float s = 0.f;
    for (; i < NN; i += stride) s += logf((float)g_deg[i] + 1.f);
    #pragma unroll
    for (int o = 16; o > 0; o >>= 1) s += __shfl_down_sync(0xffffffffu, s, o);
    __shared__ float sh[32];
    int lane = threadIdx.x & 31, wid = threadIdx.x >> 5;
    if (lane == 0) sh[wid] = s;
    __syncthreads();
    if (wid == 0) {
        float v = (lane < (int)(blockDim.x >> 5)) ? sh[lane] : 0.f;
        #pragma unroll
        for (int o = 16; o > 0; o >>= 1) v += __shfl_down_sync(0xffffffffu, v, o);
        if (lane == 0) atomicAdd(&g_delta[0], v);
    }
}

// ---------------- degree bucketing ------------------------------------------
__global__ void dhist_kernel() {
    int n = blockIdx.x * blockDim.x + threadIdx.x;
    if (n < NN) atomicAdd(&g_dcnt[min(g_deg[n], MAXD - 1)], 1);
}
__global__ void dscan_kernel() {
    if (threadIdx.x == 0) {
        int c = 0;
        for (int d = 0; d < MAXD; d++) { g_dstart[d] = c; c += g_dcnt[d]; }
    }
}
__global__ void rank_kernel() {
    int n = blockIdx.x * blockDim.x + threadIdx.x;
    if (n >= NN) return;
    int d = min(g_deg[n], MAXD - 1);
    int pos = g_dstart[d] + atomicAdd(&g_dcur[d], 1);
    g_rank[n] = pos;
    g_s2n[pos] = n;
}
__global__ void blkmap_kernel() {
    if (threadIdx.x == 0) {
        int nb = 0;
        for (int d = 0; d < MAXD; d++) {
            int c = g_dcnt[d], s = g_dstart[d];
            for (int r = 0; r < c; r += 64) {
                g_blk_deg[nb] = d;
                g_blk_row0[nb] = s + r;
                g_blk_end[nb] = s + c;
                nb++;
            }
        }
        g_nblk[0] = nb;
    }
}

// ---------------- W images ----------------------------------------------------
__global__ void whsplit_kernel(const float* __restrict__ W,
                               unsigned* __restrict__ img) {
    int i = blockIdx.x * blockDim.x + threadIdx.x;
    if (i >= 4 * 2048) return;
    int j = i >> 11, rem = i & 2047;
    int n = rem >> 4, c = rem & 15;
    int kg = j * 32 + 2 * c;
    unsigned hi, lo;
    split_pair(W[(size_t)kg * DH + n], W[(size_t)(kg + 1) * DH + n], hi, lo);
    img[(size_t)j * 4096 + n * 16 + c] = hi;
    img[(size_t)j * 4096 + 2048 + n * 16 + c] = lo;
}

// Wc(d) = W1 + amp(d) W2 + att(d) W3 (512x128) -> 16 jobs per degree.
__global__ void wcomb_kernel(const float* __restrict__ W,
                             unsigned* __restrict__ img) {
    int d = blockIdx.x;
    if (g_dcnt[d] == 0) return;
    float dlt = g_delta[0] * (1.f / (float)NN);
    float logd = logf((float)d + 1.f);
    float amp = logd / dlt;
    float att = dlt / fmaxf(logd, 1e-5f);
    unsigned* dst = img + (size_t)d * 16 * 4096;
    for (int idx = blockIdx.y * 256 + threadIdx.x; idx < 32768; idx += 32 * 256) {
        int j = idx >> 11;
        int rem = idx & 2047;
        int n = rem >> 4, c = rem & 15;
        int kg = j * 32 + 2 * c;
        float v0 = W[(size_t)(128 + kg) * DH + n]
                 + amp * W[(size_t)(640 + kg) * DH + n]
                 + att * W[(size_t)(1152 + kg) * DH + n];
        float v1 = W[(size_t)(129 + kg) * DH + n]
                 + amp * W[(size_t)(641 + kg) * DH + n]
                 + att * W[(size_t)(1153 + kg) * DH + n];
        unsigned hi, lo;
        split_pair(v0, v1, hi, lo);
        dst[(size_t)j * 4096 + n * 16 + c] = hi;
        dst[(size_t)j * 4096 + 2048 + n * 16 + c] = lo;
    }
}

// ---------------- x / h split (slot-permuted) -------------------------------
__global__ void xsplit_kernel(const float* __restrict__ x) {
    int i = blockIdx.x * blockDim.x + threadIdx.x;
    if (i >= NN * 64) return;
    int n = i >> 6, p = i & 63;
    int slot = g_rank[n];
    unsigned hi, lo;
    split_pair(x[(size_t)n * DH + 2 * p], x[(size_t)n * DH + 2 * p + 1], hi, lo);
    g_Hh[(size_t)slot * 64 + p] = hi;
    g_Hl[(size_t)slot * 64 + p] = lo;
}

// ---------------- aggregation (warp per node) -> slot-permuted image ---------
// 256 threads = 8 warps, warp = one node, lane owns 4 features (float4).
__global__ __launch_bounds__(256) void agg_kernel(const float* __restrict__ h) {
    int wid = threadIdx.x >> 5;
    int lane = threadIdx.x & 31;
    int n = blockIdx.x * 8 + wid;
    if (n >= NN) return;
    int beg = g_off[n], end = g_off[n + 1];
    int d = end - beg;

    float4 s = make_float4(0.f, 0.f, 0.f, 0.f);
    float4 ss = make_float4(0.f, 0.f, 0.f, 0.f);
    float ninf = __int_as_float(0xff800000), pinf = __int_as_float(0x7f800000);
    float4 mx = make_float4(ninf, ninf, ninf, ninf);
    float4 mn = make_float4(pinf, pinf, pinf, pinf);

    const float4* hv = (const float4*)h;
    int col = lane;           // float4 column 0..31

    int e = beg;
    for (; e + 4 <= end; e += 4) {
        int s0 = g_csr[e], s1 = g_csr[e + 1], s2 = g_csr[e + 2], s3 = g_csr[e + 3];
        float4 m0 = hv[(size_t)s0 * 32 + col];
        float4 m1 = hv[(size_t)s1 * 32 + col];
        float4 m2 = hv[(size_t)s2 * 32 + col];
        float4 m3 = hv[(size_t)s3 * 32 + col];
        s.x += m0.x + m1.x + m2.x + m3.x;
        s.y += m0.y + m1.y + m2.y + m3.y;
        s.z += m0.z + m1.z + m2.z + m3.z;
        s.w += m0.w + m1.w + m2.w + m3.w;
        ss.x += m0.x * m0.x + m1.x * m1.x + m2.x * m2.x + m3.x * m3.x;
        ss.y += m0.y * m0.y + m1.y * m1.y + m2.y * m2.y + m3.y * m3.y;
        ss.z += m0.z * m0.z + m1.z * m1.z + m2.z * m2.z + m3.z * m3.z;
        ss.w += m0.w * m0.w + m1.w * m1.w + m2.w * m2.w + m3.w * m3.w;
        mx.x = fmaxf(fmaxf(mx.x, m0.x), fmaxf(m1.x, fmaxf(m2.x, m3.x)));
        mx.y = fmaxf(fmaxf(mx.y, m0.y), fmaxf(m1.y, fmaxf(m2.y, m3.y)));
        mx.z = fmaxf(fmaxf(mx.z, m0.z), fmaxf(m1.z, fmaxf(m2.z, m3.z)));
        mx.w = fmaxf(fmaxf(mx.w, m0.w), fmaxf(m1.w, fmaxf(m2.w, m3.w)));
        mn.x = fminf(fminf(mn.x, m0.x), fminf(m1.x, fminf(m2.x, m3.x)));
        mn.y = fminf(fminf(mn.y, m0.y), fminf(m1.y, fminf(m2.y, m3.y)));
        mn.z = fminf(fminf(mn.z, m0.z), fminf(m1.z, fminf(m2.z, m3.z)));
        mn.w = fminf(fminf(mn.w, m0.w), fminf(m1.w, fminf(m2.w, m3.w)));
    }
    for (; e < end; e++) {
        int s0 = g_csr[e];
        float4 m0 = hv[(size_t)s0 * 32 + col];
        s.x += m0.x; s.y += m0.y; s.z += m0.z; s.w += m0.w;
        ss.x += m0.x * m0.x; ss.y += m0.y * m0.y;
        ss.z += m0.z * m0.z; ss.w += m0.w * m0.w;
        mx.x = fmaxf(mx.x, m0.x); mx.y = fmaxf(mx.y, m0.y);
        mx.z = fmaxf(mx.z, m0.z); mx.w = fmaxf(mx.w, m0.w);
        mn.x = fminf(mn.x, m0.x); mn.y = fminf(mn.y, m0.y);
        mn.z = fminf(mn.z, m0.z); mn.w = fminf(mn.w, m0.w);
    }

    float inv = 1.f / fmaxf((float)d, 1.f);
    float mean[4], stdv[4], mxa[4], mna[4];
    float* sp = (float*)&s;
    float* ssp = (float*)&ss;
    float* mxp = (float*)&mx;
    float* mnp = (float*)&mn;
    #pragma unroll
    for (int i = 0; i < 4; i++) {
        mean[i] = sp[i] * inv;
        float var = fmaxf(ssp[i] * inv - mean[i] * mean[i], 0.f);
        stdv[i] = sqrtf(var + 1e-5f);
        mxa[i] = (d == 0) ? 0.f : mxp[i];
        mna[i] = (d == 0) ? 0.f : mnp[i];
    }

    size_t rowb = (size_t)g_rank[n] * 256;
    unsigned hi, lo;
    // mean: pairs 2*lane, 2*lane+1
    split_pair(mean[0], mean[1], hi, lo);
    g_Agh[rowb + 2 * lane] = hi;     g_Agl[rowb + 2 * lane] = lo;
    split_pair(mean[2], mean[3], hi, lo);
    g_Agh[rowb + 2 * lane + 1] = hi; g_Agl[rowb + 2 * lane + 1] = lo;
    // max: offset 64
    split_pair(mxa[0], mxa[1], hi, lo);
    g_Agh[rowb + 64 + 2 * lane] = hi;     g_Agl[rowb + 64 + 2 * lane] = lo;
    split_pair(mxa[2], mxa[3], hi, lo);
    g_Agh[rowb + 64 + 2 * lane + 1] = hi; g_Agl[rowb + 64 + 2 * lane + 1] = lo;
    // min: offset 128
    split_pair(mna[0], mna[1], hi, lo);
    g_Agh[rowb + 128 + 2 * lane] = hi;     g_Agl[rowb + 128 + 2 * lane] = lo;
    split_pair(mna[2], mna[3], hi, lo);
    g_Agh[rowb + 128 + 2 * lane + 1] = hi; g_Agl[rowb + 128 + 2 * lane + 1] = lo;
    // std: offset 192
    split_pair(stdv[0], stdv[1], hi, lo);
    g_Agh[rowb + 192 + 2 * lane] = hi;     g_Agl[rowb + 192 + 2 * lane] = lo;
    split_pair(stdv[2], stdv[3], hi, lo);
    g_Agh[rowb + 192 + 2 * lane + 1] = hi; g_Agl[rowb + 192 + 2 * lane + 1] = lo;
}

// ---------------- bf16x3 GEMM, degree-bucketed -------------------------------
__global__ __launch_bounds__(256, 2) void gemm_deg_kernel(
        const unsigned* __restrict__ WhImg, const unsigned* __restrict__ WcImg,
        const float* __restrict__ bias, float* __restrict__ hout,
        int write_split) {
    int b = blockIdx.x;
    if (b >= g_nblk[0]) return;
    extern __shared__ unsigned smem_u[];
    const uint32_t sbase = smem_u32(smem_u);

    const int row0 = g_blk_row0[b];
    const int blkend = g_blk_end[b];
    const unsigned* Wc = WcImg + (size_t)g_blk_deg[b] * 16 * 4096;

    const int tid = threadIdx.x;
    const int lane = tid & 31, wid = tid >> 5;
    const int warp_m = wid >> 2;   // 0..1 (32 rows)
    const int warp_n = wid & 3;    // 0..3 (32 cols)
    const int lr = lane >> 2, lc = lane & 3;
    const int lg = lane >> 3, l8 = lane & 7;
    const int a_row = ((lg & 1) << 3) + l8;
    const int a_col = (lg >> 1) << 2;
    const int b_row = ((lg >> 1) << 3) + l8;
    const int b_col = (lg & 1) << 2;
    const int a_base = (warp_m * 32 + a_row) * 20 + a_col;
    const int b_base = 2560 + (warp_n * 32 + b_row) * 20 + b_col;

    float acc[2][4][4];
    #pragma unroll
    for (int mt = 0; mt < 2; mt++)
        #pragma unroll
        for (int nt = 0; nt < 4; nt++)
            #pragma unroll
            for (int e = 0; e < 4; e++) acc[mt][nt][e] = 0.f;

    auto load_stage = [&](int j, int slot) {
        uint32_t base = sbase + slot * (STGU * 4);
        const unsigned *Ah, *Al, *Bsrc;
        int K2, coff;
        if (j < 4) {
            Ah = g_Hh; Al = g_Hl; K2 = 64; coff = j * 16;
            Bsrc = WhImg + (size_t)j * 4096;
        } else {
            Ah = g_Agh; Al = g_Agl; K2 = 256; coff = (j - 4) * 16;
            Bsrc = Wc + (size_t)(j - 4) * 4096;
        }
        #pragma unroll
        for (int c0 = 0; c0 < 6; c0++) {
            int c = c0 * 256 + tid;
            uint32_t dst;
            const unsigned* src;
            if (c < 512) {
                int half = (c >= 256) ? 1 : 0;
                int rem = c - half * 256;
                int r = rem >> 2, q = rem & 3;
                int slotr = min(row0 + r, blkend - 1);
                src = (half ? Al : Ah) + (size_t)slotr * K2 + coff + q * 4;
                dst = base + (half * 1280 + r * 20 + q * 4) * 4;
            } else {
                int cb = c - 512;
                int half = cb >> 9;
                int rem = cb & 511;
                int r = rem >> 2, q = rem & 3;
                src = Bsrc + half * 2048 + r * 16 + q * 4;
                dst = base + (2560 + half * 2560 + r * 20 + q * 4) * 4;
            }
            cp16(dst, src);
        }
        CP_COMMIT();
    };

    load_stage(0, 0);

    for (int j = 0; j < NJ; j++) {
        CP_WAIT0();
        __syncthreads();
        if (j + 1 < NJ) load_stage(j + 1, (j + 1) & 1);

        uint32_t st = sbase + (j & 1) * (STGU * 4);
        #pragma unroll
        for (int kb = 0; kb < 16; kb += 8) {
            unsigned ah[2][4], al[2][4];
            #pragma unroll
            for (int mt = 0; mt < 2; mt++) {
                uint32_t ad = st + (uint32_t)(a_base + mt * 320 + kb) * 4;
                ldsm4(ah[mt][0], ah[mt][1], ah[mt][2], ah[mt][3], ad);
                ldsm4(al[mt][0], al[mt][1], al[mt][2], al[mt][3], ad + 1280 * 4);
            }
            #pragma unroll
            for (int p = 0; p < 2; p++) {
                unsigned bh[4], bl[4];
                uint32_t bp = st + (uint32_t)(b_base + p * 320 + kb) * 4;
                ldsm4(bh[0], bh[1], bh[2], bh[3], bp);
                ldsm4(bl[0], bl[1], bl[2], bl[3], bp + 2560 * 4);
                #pragma unroll
                for (int q = 0; q < 2; q++) {
                    int nt = 2 * p + q;
                    #pragma unroll
                    for (int mt = 0; mt < 2; mt++) {
                        mma_bf16(acc[mt][nt], ah[mt], &bh[2 * q]);
                        mma_bf16(acc[mt][nt], al[mt], &bh[2 * q]);
                        mma_bf16(acc[mt][nt], ah[mt], &bl[2 * q]);
                    }
                }
            }
        }
    }

    // ---- epilogue: bias + relu, scatter to node order, optional h-image -----
    #pragma unroll
    for (int mt = 0; mt < 2; mt++)
        #pragma unroll
        for (int nt = 0; nt < 4; nt++) {
            int col0 = warp_n * 32 + nt * 8 + 2 * lc;
            float b0 = bias[col0], b1 = bias[col0 + 1];
            #pragma unroll
            for (int rh = 0; rh < 2; rh++) {
                int slot = row0 + warp_m * 32 + mt * 16 + lr + rh * 8;
                if (slot >= blkend) continue;
                int node = g_s2n[slot];
                int e0 = rh * 2;
                float2 v;
                v.x = fmaxf(acc[mt][nt][e0] + b0, 0.f);
                v.y = fmaxf(acc[mt][nt][e0 + 1] + b1, 0.f);
                *(float2*)&hout[(size_t)node * DH + col0] = v;
                if (write_split) {
                    unsigned hi, lo;
                    split_pair(v.x, v.y, hi, lo);
                    g_Hh[(size_t)slot * 64 + (col0 >> 1)] = hi;
                    g_Hl[(size_t)slot * 64 + (col0 >> 1)] = lo;
                }
            }
        }
}

// ---------------- pooling + bn/fc --------------------------------------------
#define POOL_NB 256
__global__ __launch_bounds__(128) void pool_kernel(
        const float* __restrict__ h, const int* __restrict__ batch) {
    int n0 = blockIdx.x * POOL_NB;
    int t = threadIdx.x;
    int nend = min(n0 + POOL_NB, NN);
    int cnt = nend - n0;
    __shared__ int sbm[POOL_NB];
    for (int i = t; i < cnt; i += 128) sbm[i] = batch[n0 + i];
    __syncthreads();
    float acc = 0.f;
    int cur = sbm[0];
    for (int i = 0; i < cnt; i++) {
        int b = sbm[i];
        if (b != cur) {
            atomicAdd(&g_pool[cur * DH + t], acc);
            acc = 0.f; cur = b;
        }
        acc += h[(size_t)(n0 + i) * DH + t];
    }
    atomicAdd(&g_pool[cur * DH + t], acc);
}

__global__ __launch_bounds__(128) void bnfc_kernel(
        const float* __restrict__ gamma, const float* __restrict__ beta,
        const float* __restrict__ fcW, const float* __restrict__ fcb,
        float* __restrict__ out) {
    __shared__ float sp[NG * DH];
    int t = threadIdx.x;
    for (int i = t; i < NG * DH; i += 128) sp[i] = g_pool[i];
    __syncthreads();
    float m = 0.f;
    #pragma unroll 4
    for (int g = 0; g < NG; g++) m += sp[g * DH + t];
    m *= (1.f / NG);
    float v = 0.f;
    #pragma unroll 4
    for (int g = 0; g < NG; g++) { float d = sp[g * DH + t] - m; v += d * d; }
    v *= (1.f / NG);
    float rs = rsqrtf(v + 1e-5f);
    float ga = gamma[t], be = beta[t];
    for (int g = 0; g < NG; g++)
        sp[g * DH + t] = (sp[g * DH + t] - m) * rs * ga + be;
    __syncthreads();
    for (int i = t; i < NG * DLAT; i += 128) {
        int g = i / DLAT, jj = i % DLAT;
        float s = fcb[jj];
        #pragma unroll 8
        for (int c = 0; c < DH; c++) s += sp[g * DH + c] * fcW[c * DLAT + jj];
        out[i] = s;
    }
}

// ---------------- launch ------------------------------------------------------
extern "C" void kernel_launch(void* const* d_in, const int* in_sizes, int n_in,
                              void* d_out, int out_size) {
    const float* x     = (const float*)d_in[0];
    const int*   ei    = (const int*)d_in[1];
    const int*   batch = (const int*)d_in[2];
    const float* W0 = (const float*)d_in[3];  const float* b0 = (const float*)d_in[4];
    const float* W1 = (const float*)d_in[5];  const float* b1 = (const float*)d_in[6];
    const float* W2 = (const float*)d_in[7];  const float* b2 = (const float*)d_in[8];
    const float* gamma = (const float*)d_in[9];
    const float* beta  = (const float*)d_in[10];
    const float* fcW   = (const float*)d_in[11];
    const float* fcb   = (const float*)d_in[12];
    float* out = (float*)d_out;

    void *p_deg, *p_cur, *p_delta, *p_pool, *p_h0, *p_h1;
    void *p_wh, *p_wc, *p_dcnt, *p_dcur;
    cudaGetSymbolAddress(&p_deg,   g_deg);
    cudaGetSymbolAddress(&p_cur,   g_cur);
    cudaGetSymbolAddress(&p_delta, g_delta);
    cudaGetSymbolAddress(&p_pool,  g_pool);
    cudaGetSymbolAddress(&p_h0,    g_h0);
    cudaGetSymbolAddress(&p_h1,    g_h1);
    cudaGetSymbolAddress(&p_wh,    g_WhImg);
    cudaGetSymbolAddress(&p_wc,    g_WcImg);
    cudaGetSymbolAddress(&p_dcnt,  g_dcnt);
    cudaGetSymbolAddress(&p_dcur,  g_dcur);
    float* h0 = (float*)p_h0;
    float* h1 = (float*)p_h1;
    unsigned* whimg = (unsigned*)p_wh;
    unsigned* wcimg = (unsigned*)p_wc;

    cudaFuncSetAttribute(gemm_deg_kernel,
                         cudaFuncAttributeMaxDynamicSharedMemorySize, SMEM_BYTES);

    cudaMemsetAsync(p_deg,   0, NN * sizeof(int));
    cudaMemsetAsync(p_cur,   0, NN * sizeof(int));
    cudaMemsetAsync(p_delta, 0, sizeof(float));
    cudaMemsetAsync(p_pool,  0, NG * DH * sizeof(float));
    cudaMemsetAsync(p_dcnt,  0, MAXD * sizeof(int));
    cudaMemsetAsync(p_dcur,  0, MAXD * sizeof(int));

    int eblocks = (NE + 1023) / 1024;
    int sblocks = (NN + 1023) / 1024;
    hist_kernel<<<eblocks, 1024>>>(ei);
    scan1_kernel<<<sblocks, 1024>>>();
    scan2_kernel<<<1, 32>>>(sblocks);
    scan3_kernel<<<sblocks, 1024>>>();
    scatter_kernel<<<eblocks, 1024>>>(ei);
    delta_kernel<<<128, 256>>>();

    // degree bucketing
    dhist_kernel<<<(NN + 255) / 256, 256>>>();
    dscan_kernel<<<1, 32>>>();
    rank_kernel<<<(NN + 255) / 256, 256>>>();
    blkmap_kernel<<<1, 32>>>();

    // W images (wcomb needs delta)
    const size_t WHL = 4 * 4096;
    const size_t WCL = (size_t)MAXD * 16 * 4096;
    whsplit_kernel<<<(4 * 2048 + 255) / 256, 256>>>(W0, whimg);
    whsplit_kernel<<<(4 * 2048 + 255) / 256, 256>>>(W1, whimg + WHL);
    whsplit_kernel<<<(4 * 2048 + 255) / 256, 256>>>(W2, whimg + 2 * WHL);
    wcomb_kernel<<<dim3(MAXD, 32), 256>>>(W0, wcimg);
    wcomb_kernel<<<dim3(MAXD, 32), 256>>>(W1, wcimg + WCL);
    wcomb_kernel<<<dim3(MAXD, 32), 256>>>(W2, wcimg + 2 * WCL);

    xsplit_kernel<<<(NN * 64 + 255) / 256, 256>>>(x);

    int ablocks = (NN + 7) / 8;   // 6250

    // layer 0
    agg_kernel<<<ablocks, 256>>>(x);
    gemm_deg_kernel<<<MAXB, 256, SMEM_BYTES>>>(whimg, wcimg, b0, h0, 1);
    // layer 1
    agg_kernel<<<ablocks, 256>>>(h0);
    gemm_deg_kernel<<<MAXB, 256, SMEM_BYTES>>>(whimg + WHL, wcimg + WCL, b1, h1, 1);
    // layer 2
    agg_kernel<<<ablocks, 256>>>(h1);
    gemm_deg_kernel<<<MAXB, 256, SMEM_BYTES>>>(whimg + 2 * WHL, wcimg + 2 * WCL,
                                               b2, h0, 0);

    pool_kernel<<<(NN + POOL_NB - 1) / POOL_NB, 128>>>(h0, batch);
    bnfc_kernel<<<1, 128>>>(gamma, beta, fcW, fcb, out);
}

// round 13
// speedup vs baseline: 3.8603x; 1.1600x over previous
#include <cuda_runtime.h>
#include <cuda_bf16.h>
#include <math.h>
#include <stdint.h>

// Problem constants (fixed by the reference)
#define NN 50000
#define NE 600000
#define NG 64
#define DH 128
#define DLAT 64
#define MAXD 128          // degree buckets (max deg ~40 for this graph)
#define NJ 20             // GEMM jobs: 4 h (k32) + 16 agg (k32); K=640
#define MAXB 1024         // fixed GEMM grid
#define STGU 7680         // u32 per smem stage
#define SMEM_BYTES (2 * STGU * 4)

// ---------------- device scratch ------------------------------------------
__device__ int   g_deg[NN];
__device__ int   g_off[NN + 1];
__device__ int   g_cur[NN];
__device__ int   g_csr[NE];
__device__ int   g_bsum[64];
__device__ float g_delta[1];
__device__ float g_h0[(size_t)NN * DH];
__device__ float g_h1[(size_t)NN * DH];
__device__ unsigned g_Hh[(size_t)NN * 64];    // slot-permuted h image hi
__device__ unsigned g_Hl[(size_t)NN * 64];
__device__ unsigned g_Agh[(size_t)NN * 256];  // slot-permuted agg image hi
__device__ unsigned g_Agl[(size_t)NN * 256];
__device__ unsigned g_WhImg[3 * 4 * 4096];    // per-layer Wh jobs
__device__ unsigned g_WcImg[(size_t)3 * MAXD * 16 * 4096]; // per (layer,deg) Wc jobs
__device__ int   g_dcnt[MAXD];
__device__ int   g_dstart[MAXD];
__device__ int   g_dcur[MAXD];
__device__ int   g_rank[NN];      // node -> slot
__device__ int   g_s2n[NN];       // slot -> node
__device__ int   g_blk_deg[MAXB];
__device__ int   g_blk_row0[MAXB];
__device__ int   g_blk_end[MAXB];
__device__ int   g_nblk[1];
__device__ float g_pool[NG * DH];

// ---------------- helpers --------------------------------------------------
__device__ __forceinline__ void split_pair(float f0, float f1,
                                           unsigned& hi, unsigned& lo) {
    __nv_bfloat16 h0 = __float2bfloat16_rn(f0);
    __nv_bfloat16 h1 = __float2bfloat16_rn(f1);
    float r0 = f0 - __bfloat162float(h0);
    float r1 = f1 - __bfloat162float(h1);
    __nv_bfloat162 H; H.x = h0; H.y = h1;
    __nv_bfloat162 L = __floats2bfloat162_rn(r0, r1);
    hi = *reinterpret_cast<unsigned*>(&H);
    lo = *reinterpret_cast<unsigned*>(&L);
}
__device__ __forceinline__ void mma_bf16(float* d, const unsigned* a,
                                         const unsigned* b) {
    asm volatile(
        "mma.sync.aligned.m16n8k16.row.col.f32.bf16.bf16.f32 "
        "{%0,%1,%2,%3}, {%4,%5,%6,%7}, {%8,%9}, {%0,%1,%2,%3};\n"
        : "+f"(d[0]), "+f"(d[1]), "+f"(d[2]), "+f"(d[3])
        : "r"(a[0]), "r"(a[1]), "r"(a[2]), "r"(a[3]), "r"(b[0]), "r"(b[1]));
}
__device__ __forceinline__ void ldsm4(unsigned& r0, unsigned& r1,
                                      unsigned& r2, unsigned& r3, uint32_t a) {
    asm volatile("ldmatrix.sync.aligned.m8n8.x4.shared.b16 {%0,%1,%2,%3}, [%4];"
                 : "=r"(r0), "=r"(r1), "=r"(r2), "=r"(r3) : "r"(a));
}
__device__ __forceinline__ uint32_t smem_u32(const void* p) {
    uint32_t a;
    asm("{ .reg .u64 t; cvta.to.shared.u64 t, %1; cvt.u32.u64 %0, t; }"
        : "=r"(a) : "l"(p));
    return a;
}
__device__ __forceinline__ void cp16(uint32_t dst, const void* src) {
    asm volatile("cp.async.cg.shared.global [%0], [%1], 16;"
                 :: "r"(dst), "l"(src));
}
#define CP_COMMIT() asm volatile("cp.async.commit_group;" ::: "memory")
#define CP_WAIT0()  asm volatile("cp.async.wait_group 0;" ::: "memory")

// ---------------- graph prep ----------------------------------------------
__global__ void hist_kernel(const int* __restrict__ ei) {
    int e = blockIdx.x * blockDim.x + threadIdx.x;
    int stride = gridDim.x * blockDim.x;
    for (; e < NE; e += stride) atomicAdd(&g_deg[ei[NE + e]], 1);
}
__global__ void scan1_kernel() {
    __shared__ int sh[1024];
    int b = blockIdx.x, t = threadIdx.x;
    int i = b * 1024 + t;
    int v = (i < NN) ? g_deg[i] : 0;
    sh[t] = v;
    __syncthreads();
    #pragma unroll
    for (int s = 1; s < 1024; s <<= 1) {
        int add = (t >= s) ? sh[t - s] : 0;
        __syncthreads();
        sh[t] += add;
        __syncthreads();
    }
    if (i < NN) g_off[i] = sh[t] - v;
    if (t == 1023) g_bsum[b] = sh[1023];
}
__global__ void scan2_kernel(int nblk) {
    if (threadIdx.x == 0) {
        int c = 0;
        for (int b = 0; b < nblk; b++) { int s = g_bsum[b]; g_bsum[b] = c; c += s; }
        g_off[NN] = c;
    }
}
// scan3 also zeroes g_cur / degree-bucket counters (replaces 3 memsets)
__global__ void scan3_kernel() {
    int i = blockIdx.x * 1024 + threadIdx.x;
    if (i < NN) {
        g_off[i] += g_bsum[blockIdx.x];
        g_cur[i] = 0;
    }
    if (blockIdx.x == 0 && threadIdx.x < MAXD) {
        g_dcnt[threadIdx.x] = 0;
        g_dcur[threadIdx.x] = 0;
    }
}
__global__ void scatter_kernel(const int* __restrict__ ei) {
    int e = blockIdx.x * blockDim.x + threadIdx.x;
    int stride = gridDim.x * blockDim.x;
    for (; e < NE; e += stride) {
        int dst = ei[NE + e];
        int pos = g_off[dst] + atomicAdd(&g_cur[dst], 1);
        g_csr[pos] = ei[e];
    }
}
// fused: delta accumulation + degree histogram (one pass over nodes)
__global__ void delta_dhist_kernel() {
    int n = blockIdx.x * blockDim.x + threadIdx.x;
    float s = 0.f;
    if (n < NN) {
        int d = g_deg[n];
        s = logf((float)d + 1.f);
        atomicAdd(&g_dcnt[min(d, MAXD - 1)], 1);
    }
    #pragma unroll
    for (int o = 16; o > 0; o >>= 1) s += __shfl_down_sync(0xffffffffu, s, o);
    __shared__ float sh[8];
    int lane = threadIdx.x & 31, wid = threadIdx.x >> 5;
    if (lane == 0) sh[wid] = s;
    __syncthreads();
    if (wid == 0) {
        float v = (lane < 8) ? sh[lane] : 0.f;
        #pragma unroll
        for (int o = 4; o > 0; o >>= 1) v += __shfl_down_sync(0xffffffffu, v, o);
        if (lane == 0) atomicAdd(&g_delta[0], v);
    }
}
// fused: degree-bucket exclusive scan + block map (both serial, single block)
__global__ void dscan_blkmap_kernel() {
    if (threadIdx.x == 0) {
        int c = 0;
        for (int d = 0; d < MAXD; d++) { g_dstart[d] = c; c += g_dcnt[d]; }
        int nb = 0;
        for (int d = 0; d < MAXD; d++) {
            int cnt = g_dcnt[d], s = g_dstart[d];
            for (int r = 0; r < cnt; r += 64) {
                g_blk_deg[nb] = d;
                g_blk_row0[nb] = s + r;
                g_blk_end[nb] = s + cnt;
                nb++;
            }
        }
        g_nblk[0] = nb;
    }
}
__global__ void rank_kernel() {
    int n = blockIdx.x * blockDim.x + threadIdx.x;
    if (n >= NN) return;
    int d = min(g_deg[n], MAXD - 1);
    int pos = g_dstart[d] + atomicAdd(&g_dcur[d], 1);
    g_rank[n] = pos;
    g_s2n[pos] = n;
}

// ---------------- W images ----------------------------------------------------
__global__ void whsplit_kernel(const float* __restrict__ W,
                               unsigned* __restrict__ img) {
    int i = blockIdx.x * blockDim.x + threadIdx.x;
    if (i >= 4 * 2048) return;
    int n = i & 127;            // coalesced reads over n
    int rest = i >> 7;
    int c = rest & 15;
    int j = rest >> 4;
    int kg = j * 32 + 2 * c;
    unsigned hi, lo;
    split_pair(W[(size_t)kg * DH + n], W[(size_t)(kg + 1) * DH + n], hi, lo);
    img[(size_t)j * 4096 + n * 16 + c] = hi;
    img[(size_t)j * 4096 + 2048 + n * 16 + c] = lo;
}

// Wc(d) = W1 + amp(d) W2 + att(d) W3 (512x128) -> 16 jobs per degree.
// Index mapped so consecutive threads read consecutive n (coalesced).
__global__ void wcomb_kernel(const float* __restrict__ W,
                             unsigned* __restrict__ img) {
    int d = blockIdx.x;
    if (g_dcnt[d] == 0) return;
    float dlt = g_delta[0] * (1.f / (float)NN);
    float logd = logf((float)d + 1.f);
    float amp = logd / dlt;
    float att = dlt / fmaxf(logd, 1e-5f);
    unsigned* dst = img + (size_t)d * 16 * 4096;
    for (int idx = blockIdx.y * 256 + threadIdx.x; idx < 32768; idx += 32 * 256) {
        int n = idx & 127;
        int rest = idx >> 7;
        int c = rest & 15;
        int j = rest >> 4;
        int kg = j * 32 + 2 * c;
        float v0 = W[(size_t)(128 + kg) * DH + n]
                 + amp * W[(size_t)(640 + kg) * DH + n]
                 + att * W[(size_t)(1152 + kg) * DH + n];
        float v1 = W[(size_t)(129 + kg) * DH + n]
                 + amp * W[(size_t)(641 + kg) * DH + n]
                 + att * W[(size_t)(1153 + kg) * DH + n];
        unsigned hi, lo;
        split_pair(v0, v1, hi, lo);
        dst[(size_t)j * 4096 + n * 16 + c] = hi;
        dst[(size_t)j * 4096 + 2048 + n * 16 + c] = lo;
    }
}

// ---------------- x / h split (slot-permuted) -------------------------------
__global__ void xsplit_kernel(const float* __restrict__ x) {
    int i = blockIdx.x * blockDim.x + threadIdx.x;
    if (i >= NN * 64) return;
    int n = i >> 6, p = i & 63;
    int slot = g_rank[n];
    unsigned hi, lo;
    split_pair(x[(size_t)n * DH + 2 * p], x[(size_t)n * DH + 2 * p + 1], hi, lo);
    g_Hh[(size_t)slot * 64 + p] = hi;
    g_Hl[(size_t)slot * 64 + p] = lo;
}

// ---------------- aggregation (warp per node) -> slot-permuted image ---------
__global__ __launch_bounds__(256) void agg_kernel(const float* __restrict__ h) {
    int wid = threadIdx.x >> 5;
    int lane = threadIdx.x & 31;
    int n = blockIdx.x * 8 + wid;
    if (n >= NN) return;
    int beg = g_off[n], end = g_off[n + 1];
    int d = end - beg;

    float4 s = make_float4(0.f, 0.f, 0.f, 0.f);
    float4 ss = make_float4(0.f, 0.f, 0.f, 0.f);
    float ninf = __int_as_float(0xff800000), pinf = __int_as_float(0x7f800000);
    float4 mx = make_float4(ninf, ninf, ninf, ninf);
    float4 mn = make_float4(pinf, pinf, pinf, pinf);

    const float4* hv = (const float4*)h;
    int col = lane;

    int e = beg;
    for (; e + 4 <= end; e += 4) {
        int s0 = g_csr[e], s1 = g_csr[e + 1], s2 = g_csr[e + 2], s3 = g_csr[e + 3];
        float4 m0 = hv[(size_t)s0 * 32 + col];
        float4 m1 = hv[(size_t)s1 * 32 + col];
        float4 m2 = hv[(size_t)s2 * 32 + col];
        float4 m3 = hv[(size_t)s3 * 32 + col];
        s.x += m0.x + m1.x + m2.x + m3.x;
        s.y += m0.y + m1.y + m2.y + m3.y;
        s.z += m0.z + m1.z + m2.z + m3.z;
        s.w += m0.w + m1.w + m2.w + m3.w;
        ss.x += m0.x * m0.x + m1.x * m1.x + m2.x * m2.x + m3.x * m3.x;
        ss.y += m0.y * m0.y + m1.y * m1.y + m2.y * m2.y + m3.y * m3.y;
        ss.z += m0.z * m0.z + m1.z * m1.z + m2.z * m2.z + m3.z * m3.z;
        ss.w += m0.w * m0.w + m1.w * m1.w + m2.w * m2.w + m3.w * m3.w;
        mx.x = fmaxf(fmaxf(mx.x, m0.x), fmaxf(m1.x, fmaxf(m2.x, m3.x)));
        mx.y = fmaxf(fmaxf(mx.y, m0.y), fmaxf(m1.y, fmaxf(m2.y, m3.y)));
        mx.z = fmaxf(fmaxf(mx.z, m0.z), fmaxf(m1.z, fmaxf(m2.z, m3.z)));
        mx.w = fmaxf(fmaxf(mx.w, m0.w), fmaxf(m1.w, fmaxf(m2.w, m3.w)));
        mn.x = fminf(fminf(mn.x, m0.x), fminf(m1.x, fminf(m2.x, m3.x)));
        mn.y = fminf(fminf(mn.y, m0.y), fminf(m1.y, fminf(m2.y, m3.y)));
        mn.z = fminf(fminf(mn.z, m0.z), fminf(m1.z, fminf(m2.z, m3.z)));
        mn.w = fminf(fminf(mn.w, m0.w), fminf(m1.w, fminf(m2.w, m3.w)));
    }
    for (; e < end; e++) {
        int s0 = g_csr[e];
        float4 m0 = hv[(size_t)s0 * 32 + col];
        s.x += m0.x; s.y += m0.y; s.z += m0.z; s.w += m0.w;
        ss.x += m0.x * m0.x; ss.y += m0.y * m0.y;
        ss.z += m0.z * m0.z; ss.w += m0.w * m0.w;
        mx.x = fmaxf(mx.x, m0.x); mx.y = fmaxf(mx.y, m0.y);
        mx.z = fmaxf(mx.z, m0.z); mx.w = fmaxf(mx.w, m0.w);
        mn.x = fminf(mn.x, m0.x); mn.y = fminf(mn.y, m0.y);
        mn.z = fminf(mn.z, m0.z); mn.w = fminf(mn.w, m0.w);
    }

    float inv = 1.f / fmaxf((float)d, 1.f);
    float mean[4], stdv[4], mxa[4], mna[4];
    float* sp = (float*)&s;
    float* ssp = (float*)&ss;
    float* mxp = (float*)&mx;
    float* mnp = (float*)&mn;
    #pragma unroll
    for (int i = 0; i < 4; i++) {
        mean[i] = sp[i] * inv;
        float var = fmaxf(ssp[i] * inv - mean[i] * mean[i], 0.f);
        stdv[i] = sqrtf(var + 1e-5f);
        mxa[i] = (d == 0) ? 0.f : mxp[i];
        mna[i] = (d == 0) ? 0.f : mnp[i];
    }

    size_t rowb = (size_t)g_rank[n] * 256;
    unsigned hi, lo;
    split_pair(mean[0], mean[1], hi, lo);
    g_Agh[rowb + 2 * lane] = hi;     g_Agl[rowb + 2 * lane] = lo;
    split_pair(mean[2], mean[3], hi, lo);
    g_Agh[rowb + 2 * lane + 1] = hi; g_Agl[rowb + 2 * lane + 1] = lo;
    split_pair(mxa[0], mxa[1], hi, lo);
    g_Agh[rowb + 64 + 2 * lane] = hi;     g_Agl[rowb + 64 + 2 * lane] = lo;
    split_pair(mxa[2], mxa[3], hi, lo);
    g_Agh[rowb + 64 + 2 * lane + 1] = hi; g_Agl[rowb + 64 + 2 * lane + 1] = lo;
    split_pair(mna[0], mna[1], hi, lo);
    g_Agh[rowb + 128 + 2 * lane] = hi;     g_Agl[rowb + 128 + 2 * lane] = lo;
    split_pair(mna[2], mna[3], hi, lo);
    g_Agh[rowb + 128 + 2 * lane + 1] = hi; g_Agl[rowb + 128 + 2 * lane + 1] = lo;
    split_pair(stdv[0], stdv[1], hi, lo);
    g_Agh[rowb + 192 + 2 * lane] = hi;     g_Agl[rowb + 192 + 2 * lane] = lo;
    split_pair(stdv[2], stdv[3], hi, lo);
    g_Agh[rowb + 192 + 2 * lane + 1] = hi; g_Agl[rowb + 192 + 2 * lane + 1] = lo;
}

// ---------------- bf16x3 GEMM, degree-bucketed -------------------------------
__global__ __launch_bounds__(256, 2) void gemm_deg_kernel(
        const unsigned* __restrict__ WhImg, const unsigned* __restrict__ WcImg,
        const float* __restrict__ bias, float* __restrict__ hout,
        int write_split) {
    int b = blockIdx.x;
    if (b >= g_nblk[0]) return;
    extern __shared__ unsigned smem_u[];
    const uint32_t sbase = smem_u32(smem_u);

    const int row0 = g_blk_row0[b];
    const int blkend = g_blk_end[b];
    const unsigned* Wc = WcImg + (size_t)g_blk_deg[b] * 16 * 4096;

    const int tid = threadIdx.x;
    const int lane = tid & 31, wid = tid >> 5;
    const int warp_m = wid >> 2;   // 0..1 (32 rows)
    const int warp_n = wid & 3;    // 0..3 (32 cols)
    const int lr = lane >> 2, lc = lane & 3;
    const int lg = lane >> 3, l8 = lane & 7;
    const int a_row = ((lg & 1) << 3) + l8;
    const int a_col = (lg >> 1) << 2;
    const int b_row = ((lg >> 1) << 3) + l8;
    const int b_col = (lg & 1) << 2;
    const int a_base = (warp_m * 32 + a_row) * 20 + a_col;
    const int b_base = 2560 + (warp_n * 32 + b_row) * 20 + b_col;

    float acc[2][4][4];
    #pragma unroll
    for (int mt = 0; mt < 2; mt++)
        #pragma unroll
        for (int nt = 0; nt < 4; nt++)
            #pragma unroll
            for (int e = 0; e < 4; e++) acc[mt][nt][e] = 0.f;

    auto load_stage = [&](int j, int slot) {
        uint32_t base = sbase + slot * (STGU * 4);
        const unsigned *Ah, *Al, *Bsrc;
        int K2, coff;
        if (j < 4) {
            Ah = g_Hh; Al = g_Hl; K2 = 64; coff = j * 16;
            Bsrc = WhImg + (size_t)j * 4096;
        } else {
            Ah = g_Agh; Al = g_Agl; K2 = 256; coff = (j - 4) * 16;
            Bsrc = Wc + (size_t)(j - 4) * 4096;
        }
        #pragma unroll
        for (int c0 = 0; c0 < 6; c0++) {
            int c = c0 * 256 + tid;
            uint32_t dst;
            const unsigned* src;
            if (c < 512) {
                int half = (c >= 256) ? 1 : 0;
                int rem = c - half * 256;
                int r = rem >> 2, q = rem & 3;
                int slotr = min(row0 + r, blkend - 1);
                src = (half ? Al : Ah) + (size_t)slotr * K2 + coff + q * 4;
                dst = base + (half * 1280 + r * 20 + q * 4) * 4;
            } else {
                int cb = c - 512;
                int half = cb >> 9;
                int rem = cb & 511;
                int r = rem >> 2, q = rem & 3;
                src = Bsrc + half * 2048 + r * 16 + q * 4;
                dst = base + (2560 + half * 2560 + r * 20 + q * 4) * 4;
            }
            cp16(dst, src);
        }
        CP_COMMIT();
    };

    load_stage(0, 0);

    for (int j = 0; j < NJ; j++) {
        CP_WAIT0();
        __syncthreads();
        if (j + 1 < NJ) load_stage(j + 1, (j + 1) & 1);

        uint32_t st = sbase + (j & 1) * (STGU * 4);
        #pragma unroll
        for (int kb = 0; kb < 16; kb += 8) {
            unsigned ah[2][4], al[2][4];
            #pragma unroll
            for (int mt = 0; mt < 2; mt++) {
                uint32_t ad = st + (uint32_t)(a_base + mt * 320 + kb) * 4;
                ldsm4(ah[mt][0], ah[mt][1], ah[mt][2], ah[mt][3], ad);
                ldsm4(al[mt][0], al[mt][1], al[mt][2], al[mt][3], ad + 1280 * 4);
            }
            #pragma unroll
            for (int p = 0; p < 2; p++) {
                unsigned bh[4], bl[4];
                uint32_t bp = st + (uint32_t)(b_base + p * 320 + kb) * 4;
                ldsm4(bh[0], bh[1], bh[2], bh[3], bp);
                ldsm4(bl[0], bl[1], bl[2], bl[3], bp + 2560 * 4);
                #pragma unroll
                for (int q = 0; q < 2; q++) {
                    int nt = 2 * p + q;
                    #pragma unroll
                    for (int mt = 0; mt < 2; mt++) {
                        mma_bf16(acc[mt][nt], ah[mt], &bh[2 * q]);
                        mma_bf16(acc[mt][nt], al[mt], &bh[2 * q]);
                        mma_bf16(acc[mt][nt], ah[mt], &bl[2 * q]);
                    }
                }
            }
        }
    }

    // ---- epilogue: bias + relu, scatter to node order, optional h-image -----
    #pragma unroll
    for (int mt = 0; mt < 2; mt++)
        #pragma unroll
        for (int nt = 0; nt < 4; nt++) {
            int col0 = warp_n * 32 + nt * 8 + 2 * lc;
            float b0 = bias[col0], b1 = bias[col0 + 1];
            #pragma unroll
            for (int rh = 0; rh < 2; rh++) {
                int slot = row0 + warp_m * 32 + mt * 16 + lr + rh * 8;
                if (slot >= blkend) continue;
                int node = g_s2n[slot];
                int e0 = rh * 2;
                float2 v;
                v.x = fmaxf(acc[mt][nt][e0] + b0, 0.f);
                v.y = fmaxf(acc[mt][nt][e0 + 1] + b1, 0.f);
                *(float2*)&hout[(size_t)node * DH + col0] = v;
                if (write_split) {
                    unsigned hi, lo;
                    split_pair(v.x, v.y, hi, lo);
                    g_Hh[(size_t)slot * 64 + (col0 >> 1)] = hi;
                    g_Hl[(size_t)slot * 64 + (col0 >> 1)] = lo;
                }
            }
        }
}

// ---------------- pooling + bn/fc --------------------------------------------
#define POOL_NB 256
__global__ __launch_bounds__(128) void pool_kernel(
        const float* __restrict__ h, const int* __restrict__ batch) {
    int n0 = blockIdx.x * POOL_NB;
    int t = threadIdx.x;
    int nend = min(n0 + POOL_NB, NN);
    int cnt = nend - n0;
    __shared__ int sbm[POOL_NB];
    for (int i = t; i < cnt; i += 128) sbm[i] = batch[n0 + i];
    __syncthreads();
    float acc = 0.f;
    int cur = sbm[0];
    for (int i = 0; i < cnt; i++) {
        int b = sbm[i];
        if (b != cur) {
            atomicAdd(&g_pool[cur * DH + t], acc);
            acc = 0.f; cur = b;
        }
        acc += h[(size_t)(n0 + i) * DH + t];
    }
    atomicAdd(&g_pool[cur * DH + t], acc);
}

__global__ __launch_bounds__(512) void bnfc_kernel(
        const float* __restrict__ gamma, const float* __restrict__ beta,
        const float* __restrict__ fcW, const float* __restrict__ fcb,
        float* __restrict__ out) {
    __shared__ float sp[NG * DH];
    int t = threadIdx.x;
    for (int i = t; i < NG * DH; i += 512) sp[i] = g_pool[i];
    __syncthreads();
    if (t < 128) {
        float m = 0.f;
        #pragma unroll 4
        for (int g = 0; g < NG; g++) m += sp[g * DH + t];
        m *= (1.f / NG);
        float v = 0.f;
        #pragma unroll 4
        for (int g = 0; g < NG; g++) { float d = sp[g * DH + t] - m; v += d * d; }
        v *= (1.f / NG);
        float rs = rsqrtf(v + 1e-5f);
        float ga = gamma[t], be = beta[t];
        for (int g = 0; g < NG; g++)
            sp[g * DH + t] = (sp[g * DH + t] - m) * rs * ga + be;
    }
    __syncthreads();
    for (int i = t; i < NG * DLAT; i += 512) {
        int g = i / DLAT, jj = i % DLAT;
        float s = fcb[jj];
        #pragma unroll 8
        for (int c = 0; c < DH; c++) s += sp[g * DH + c] * fcW[c * DLAT + jj];
        out[i] = s;
    }
}

// ---------------- launch ------------------------------------------------------
extern "C" void kernel_launch(void* const* d_in, const int* in_sizes, int n_in,
                              void* d_out, int out_size) {
    const float* x     = (const float*)d_in[0];
    const int*   ei    = (const int*)d_in[1];
    const int*   batch = (const int*)d_in[2];
    const float* W0 = (const float*)d_in[3];  const float* b0 = (const float*)d_in[4];
    const float* W1 = (const float*)d_in[5];  const float* b1 = (const float*)d_in[6];
    const float* W2 = (const float*)d_in[7];  const float* b2 = (const float*)d_in[8];
    const float* gamma = (const float*)d_in[9];
    const float* beta  = (const float*)d_in[10];
    const float* fcW   = (const float*)d_in[11];
    const float* fcb   = (const float*)d_in[12];
    float* out = (float*)d_out;

    void *p_deg, *p_delta, *p_pool, *p_h0, *p_h1, *p_wh, *p_wc;
    cudaGetSymbolAddress(&p_deg,   g_deg);
    cudaGetSymbolAddress(&p_delta, g_delta);
    cudaGetSymbolAddress(&p_pool,  g_pool);
    cudaGetSymbolAddress(&p_h0,    g_h0);
    cudaGetSymbolAddress(&p_h1,    g_h1);
    cudaGetSymbolAddress(&p_wh,    g_WhImg);
    cudaGetSymbolAddress(&p_wc,    g_WcImg);
    float* h0 = (float*)p_h0;
    float* h1 = (float*)p_h1;
    unsigned* whimg = (unsigned*)p_wh;
    unsigned* wcimg = (unsigned*)p_wc;

    cudaFuncSetAttribute(gemm_deg_kernel,
                         cudaFuncAttributeMaxDynamicSharedMemorySize, SMEM_BYTES);

    cudaMemsetAsync(p_deg,   0, NN * sizeof(int));
    cudaMemsetAsync(p_delta, 0, sizeof(float));
    cudaMemsetAsync(p_pool,  0, NG * DH * sizeof(float));

    int eblocks = (NE + 1023) / 1024;
    int sblocks = (NN + 1023) / 1024;
    hist_kernel<<<eblocks, 1024>>>(ei);
    scan1_kernel<<<sblocks, 1024>>>();
    scan2_kernel<<<1, 32>>>(sblocks);
    scan3_kernel<<<sblocks, 1024>>>();    // also zeroes g_cur / g_dcnt / g_dcur
    scatter_kernel<<<eblocks, 1024>>>(ei);
    delta_dhist_kernel<<<(NN + 255) / 256, 256>>>();
    dscan_blkmap_kernel<<<1, 32>>>();
    rank_kernel<<<(NN + 255) / 256, 256>>>();

    // W images (wcomb needs delta)
    const size_t WHL = 4 * 4096;
    const size_t WCL = (size_t)MAXD * 16 * 4096;
    whsplit_kernel<<<(4 * 2048 + 255) / 256, 256>>>(W0, whimg);
    whsplit_kernel<<<(4 * 2048 + 255) / 256, 256>>>(W1, whimg + WHL);
    whsplit_kernel<<<(4 * 2048 + 255) / 256, 256>>>(W2, whimg + 2 * WHL);
    wcomb_kernel<<<dim3(MAXD, 32), 256>>>(W0, wcimg);
    wcomb_kernel<<<dim3(MAXD, 32), 256>>>(W1, wcimg + WCL);
    wcomb_kernel<<<dim3(MAXD, 32), 256>>>(W2, wcimg + 2 * WCL);

    xsplit_kernel<<<(NN * 64 + 255) / 256, 256>>>(x);

    int ablocks = (NN + 7) / 8;   // 6250

    // layer 0
    agg_kernel<<<ablocks, 256>>>(x);
    gemm_deg_kernel<<<MAXB, 256, SMEM_BYTES>>>(whimg, wcimg, b0, h0, 1);
    // layer 1
    agg_kernel<<<ablocks, 256>>>(h0);
    gemm_deg_kernel<<<MAXB, 256, SMEM_BYTES>>>(whimg + WHL, wcimg + WCL, b1, h1, 1);
    // layer 2
    agg_kernel<<<ablocks, 256>>>(h1);
    gemm_deg_kernel<<<MAXB, 256, SMEM_BYTES>>>(whimg + 2 * WHL, wcimg + 2 * WCL,
                                               b2, h0, 0);

    pool_kernel<<<(NN + POOL_NB - 1) / POOL_NB, 128>>>(h0, batch);
    bnfc_kernel<<<1, 512>>>(gamma, beta, fcW, fcb, out);
}

// round 14
// speedup vs baseline: 3.9513x; 1.0236x over previous
#include <cuda_runtime.h>
#include <cuda_bf16.h>
#include <math.h>
#include <stdint.h>

// Problem constants (fixed by the reference)
#define NN 50000
#define NE 600000
#define NG 64
#define DH 128
#define DLAT 64
#define MAXD 128          // degree buckets (max deg ~40 for this graph)
#define NJ 20             // GEMM jobs: 4 h (k32) + 16 agg (k32); K=640
#define MAXB 1024         // fixed GEMM grid
#define STGU 7680         // u32 per smem stage
#define NSTG 3
#define SMEM_BYTES (NSTG * STGU * 4)

// ---------------- device scratch ------------------------------------------
__device__ int   g_deg[NN];
__device__ int   g_off[NN + 1];
__device__ int   g_cur[NN];
__device__ int   g_csr[NE];
__device__ int   g_bsum[64];
__device__ float g_delta[1];
__device__ float g_h0[(size_t)NN * DH];
__device__ float g_h1[(size_t)NN * DH];
__device__ unsigned g_Hh[(size_t)NN * 64];    // slot-permuted h image hi
__device__ unsigned g_Hl[(size_t)NN * 64];
__device__ unsigned g_Agh[(size_t)NN * 256];  // slot-permuted agg image hi
__device__ unsigned g_Agl[(size_t)NN * 256];
__device__ unsigned g_WhImg[3 * 4 * 4096];    // per-layer Wh jobs
__device__ unsigned g_WcImg[(size_t)3 * MAXD * 16 * 4096]; // per (layer,deg) Wc jobs
__device__ int   g_dcnt[MAXD];
__device__ int   g_dstart[MAXD];
__device__ int   g_dcur[MAXD];
__device__ int   g_rank[NN];      // node -> slot
__device__ int   g_s2n[NN];       // slot -> node
__device__ int   g_blk_deg[MAXB];
__device__ int   g_blk_row0[MAXB];
__device__ int   g_blk_end[MAXB];
__device__ int   g_nblk[1];
__device__ float g_pool[NG * DH];

// ---------------- helpers --------------------------------------------------
__device__ __forceinline__ void split_pair(float f0, float f1,
                                           unsigned& hi, unsigned& lo) {
    __nv_bfloat16 h0 = __float2bfloat16_rn(f0);
    __nv_bfloat16 h1 = __float2bfloat16_rn(f1);
    float r0 = f0 - __bfloat162float(h0);
    float r1 = f1 - __bfloat162float(h1);
    __nv_bfloat162 H; H.x = h0; H.y = h1;
    __nv_bfloat162 L = __floats2bfloat162_rn(r0, r1);
    hi = *reinterpret_cast<unsigned*>(&H);
    lo = *reinterpret_cast<unsigned*>(&L);
}
__device__ __forceinline__ void mma_bf16(float* d, const unsigned* a,
                                         const unsigned* b) {
    asm volatile(
        "mma.sync.aligned.m16n8k16.row.col.f32.bf16.bf16.f32 "
        "{%0,%1,%2,%3}, {%4,%5,%6,%7}, {%8,%9}, {%0,%1,%2,%3};\n"
        : "+f"(d[0]), "+f"(d[1]), "+f"(d[2]), "+f"(d[3])
        : "r"(a[0]), "r"(a[1]), "r"(a[2]), "r"(a[3]), "r"(b[0]), "r"(b[1]));
}
__device__ __forceinline__ void ldsm4(unsigned& r0, unsigned& r1,
                                      unsigned& r2, unsigned& r3, uint32_t a) {
    asm volatile("ldmatrix.sync.aligned.m8n8.x4.shared.b16 {%0,%1,%2,%3}, [%4];"
                 : "=r"(r0), "=r"(r1), "=r"(r2), "=r"(r3) : "r"(a));
}
__device__ __forceinline__ uint32_t smem_u32(const void* p) {
    uint32_t a;
    asm("{ .reg .u64 t; cvta.to.shared.u64 t, %1; cvt.u32.u64 %0, t; }"
        : "=r"(a) : "l"(p));
    return a;
}
__device__ __forceinline__ void cp16(uint32_t dst, const void* src) {
    asm volatile("cp.async.cg.shared.global [%0], [%1], 16;"
                 :: "r"(dst), "l"(src));
}
#define CP_COMMIT() asm volatile("cp.async.commit_group;" ::: "memory")
#define CP_WAIT1()  asm volatile("cp.async.wait_group 1;" ::: "memory")

// ---------------- graph prep ----------------------------------------------
__global__ void hist_kernel(const int* __restrict__ ei) {
    int e = blockIdx.x * blockDim.x + threadIdx.x;
    int stride = gridDim.x * blockDim.x;
    for (; e < NE; e += stride) atomicAdd(&g_deg[ei[NE + e]], 1);
}
__global__ void scan1_kernel() {
    __shared__ int sh[1024];
    int b = blockIdx.x, t = threadIdx.x;
    int i = b * 1024 + t;
    int v = (i < NN) ? g_deg[i] : 0;
    sh[t] = v;
    __syncthreads();
    #pragma unroll
    for (int s = 1; s < 1024; s <<= 1) {
        int add = (t >= s) ? sh[t - s] : 0;
        __syncthreads();
        sh[t] += add;
        __syncthreads();
    }
    if (i < NN) g_off[i] = sh[t] - v;
    if (t == 1023) g_bsum[b] = sh[1023];
}
__global__ void scan2_kernel(int nblk) {
    if (threadIdx.x == 0) {
        int c = 0;
        for (int b = 0; b < nblk; b++) { int s = g_bsum[b]; g_bsum[b] = c; c += s; }
        g_off[NN] = c;
    }
}
// scan3 also zeroes g_cur / degree-bucket counters
__global__ void scan3_kernel() {
    int i = blockIdx.x * 1024 + threadIdx.x;
    if (i < NN) {
        g_off[i] += g_bsum[blockIdx.x];
        g_cur[i] = 0;
    }
    if (blockIdx.x == 0 && threadIdx.x < MAXD) {
        g_dcnt[threadIdx.x] = 0;
        g_dcur[threadIdx.x] = 0;
    }
}
__global__ void scatter_kernel(const int* __restrict__ ei) {
    int e = blockIdx.x * blockDim.x + threadIdx.x;
    int stride = gridDim.x * blockDim.x;
    for (; e < NE; e += stride) {
        int dst = ei[NE + e];
        int pos = g_off[dst] + atomicAdd(&g_cur[dst], 1);
        g_csr[pos] = ei[e];
    }
}
// fused: delta accumulation + degree histogram
__global__ void delta_dhist_kernel() {
    int n = blockIdx.x * blockDim.x + threadIdx.x;
    float s = 0.f;
    if (n < NN) {
        int d = g_deg[n];
        s = logf((float)d + 1.f);
        atomicAdd(&g_dcnt[min(d, MAXD - 1)], 1);
    }
    #pragma unroll
    for (int o = 16; o > 0; o >>= 1) s += __shfl_down_sync(0xffffffffu, s, o);
    __shared__ float sh[8];
    int lane = threadIdx.x & 31, wid = threadIdx.x >> 5;
    if (lane == 0) sh[wid] = s;
    __syncthreads();
    if (wid == 0) {
        float v = (lane < 8) ? sh[lane] : 0.f;
        #pragma unroll
        for (int o = 4; o > 0; o >>= 1) v += __shfl_down_sync(0xffffffffu, v, o);
        if (lane == 0) atomicAdd(&g_delta[0], v);
    }
}
// fused: degree-bucket exclusive scan + block map
__global__ void dscan_blkmap_kernel() {
    if (threadIdx.x == 0) {
        int c = 0;
        for (int d = 0; d < MAXD; d++) { g_dstart[d] = c; c += g_dcnt[d]; }
        int nb = 0;
        for (int d = 0; d < MAXD; d++) {
            int cnt = g_dcnt[d], s = g_dstart[d];
            for (int r = 0; r < cnt; r += 64) {
                g_blk_deg[nb] = d;
                g_blk_row0[nb] = s + r;
                g_blk_end[nb] = s + cnt;
                nb++;
            }
        }
        g_nblk[0] = nb;
    }
}
__global__ void rank_kernel() {
    int n = blockIdx.x * blockDim.x + threadIdx.x;
    if (n >= NN) return;
    int d = min(g_deg[n], MAXD - 1);
    int pos = g_dstart[d] + atomicAdd(&g_dcur[d], 1);
    g_rank[n] = pos;
    g_s2n[pos] = n;
}

// ---------------- W images (layer selected by blockIdx.z) -------------------
__global__ void whsplit_kernel(const float* __restrict__ Wa,
                               const float* __restrict__ Wb,
                               const float* __restrict__ Wc,
                               unsigned* __restrict__ img0) {
    int i = blockIdx.x * blockDim.x + threadIdx.x;
    if (i >= 4 * 2048) return;
    const float* W = (blockIdx.z == 0) ? Wa : (blockIdx.z == 1) ? Wb : Wc;
    unsigned* img = img0 + (size_t)blockIdx.z * 4 * 4096;
    int n = i & 127;
    int rest = i >> 7;
    int c = rest & 15;
    int j = rest >> 4;
    int kg = j * 32 + 2 * c;
    unsigned hi, lo;
    split_pair(W[(size_t)kg * DH + n], W[(size_t)(kg + 1) * DH + n], hi, lo);
    img[(size_t)j * 4096 + n * 16 + c] = hi;
    img[(size_t)j * 4096 + 2048 + n * 16 + c] = lo;
}

// Wc(d) = W1 + amp(d) W2 + att(d) W3 (512x128) -> 16 jobs per degree.
__global__ void wcomb_kernel(const float* __restrict__ Wa,
                             const float* __restrict__ Wb,
                             const float* __restrict__ Wcc,
                             unsigned* __restrict__ img0) {
    int d = blockIdx.x;
    if (g_dcnt[d] == 0) return;
    const float* W = (blockIdx.z == 0) ? Wa : (blockIdx.z == 1) ? Wb : Wcc;
    unsigned* img = img0 + (size_t)blockIdx.z * MAXD * 16 * 4096;
    float dlt = g_delta[0] * (1.f / (float)NN);
    float logd = logf((float)d + 1.f);
    float amp = logd / dlt;
    float att = dlt / fmaxf(logd, 1e-5f);
    unsigned* dst = img + (size_t)d * 16 * 4096;
    for (int idx = blockIdx.y * 256 + threadIdx.x; idx < 32768; idx += 32 * 256) {
        int n = idx & 127;
        int rest = idx >> 7;
        int c = rest & 15;
        int j = rest >> 4;
        int kg = j * 32 + 2 * c;
        float v0 = W[(size_t)(128 + kg) * DH + n]
                 + amp * W[(size_t)(640 + kg) * DH + n]
                 + att * W[(size_t)(1152 + kg) * DH + n];
        float v1 = W[(size_t)(129 + kg) * DH + n]
                 + amp * W[(size_t)(641 + kg) * DH + n]
                 + att * W[(size_t)(1153 + kg) * DH + n];
        unsigned hi, lo;
        split_pair(v0, v1, hi, lo);
        dst[(size_t)j * 4096 + n * 16 + c] = hi;
        dst[(size_t)j * 4096 + 2048 + n * 16 + c] = lo;
    }
}

// ---------------- x / h split (slot-permuted) -------------------------------
__global__ void xsplit_kernel(const float* __restrict__ x) {
    int i = blockIdx.x * blockDim.x + threadIdx.x;
    if (i >= NN * 64) return;
    int n = i >> 6, p = i & 63;
    int slot = g_rank[n];
    unsigned hi, lo;
    split_pair(x[(size_t)n * DH + 2 * p], x[(size_t)n * DH + 2 * p + 1], hi, lo);
    g_Hh[(size_t)slot * 64 + p] = hi;
    g_Hl[(size_t)slot * 64 + p] = lo;
}

// ---------------- aggregation (warp per node, MLP=8) ------------------------
__global__ __launch_bounds__(256) void agg_kernel(const float* __restrict__ h) {
    int wid = threadIdx.x >> 5;
    int lane = threadIdx.x & 31;
    int n = blockIdx.x * 8 + wid;
    if (n >= NN) return;
    int beg = g_off[n], end = g_off[n + 1];
    int d = end - beg;

    float s[4] = {0.f, 0.f, 0.f, 0.f};
    float ss[4] = {0.f, 0.f, 0.f, 0.f};
    float mx[4], mn[4];
    #pragma unroll
    for (int i = 0; i < 4; i++) {
        mx[i] = __int_as_float(0xff800000);
        mn[i] = __int_as_float(0x7f800000);
    }

    const float4* hv = (const float4*)h;
    int col = lane;

    int e = beg;
    for (; e + 8 <= end; e += 8) {
        int idx[8];
        #pragma unroll
        for (int u = 0; u < 8; u++) idx[u] = g_csr[e + u];
        float4 m[8];
        #pragma unroll
        for (int u = 0; u < 8; u++) m[u] = hv[(size_t)idx[u] * 32 + col];
        #pragma unroll
        for (int u = 0; u < 8; u++) {
            const float* mp = (const float*)&m[u];
            #pragma unroll
            for (int i = 0; i < 4; i++) {
                float v = mp[i];
                s[i] += v; ss[i] += v * v;
                mx[i] = fmaxf(mx[i], v); mn[i] = fminf(mn[i], v);
            }
        }
    }
    for (; e < end; e++) {
        float4 m0 = hv[(size_t)g_csr[e] * 32 + col];
        const float* mp = (const float*)&m0;
        #pragma unroll
        for (int i = 0; i < 4; i++) {
            float v = mp[i];
            s[i] += v; ss[i] += v * v;
            mx[i] = fmaxf(mx[i], v); mn[i] = fminf(mn[i], v);
        }
    }

    float inv = 1.f / fmaxf((float)d, 1.f);
    float mean[4], stdv[4], mxa[4], mna[4];
    #pragma unroll
    for (int i = 0; i < 4; i++) {
        mean[i] = s[i] * inv;
        float var = fmaxf(ss[i] * inv - mean[i] * mean[i], 0.f);
        stdv[i] = sqrtf(var + 1e-5f);
        mxa[i] = (d == 0) ? 0.f : mx[i];
        mna[i] = (d == 0) ? 0.f : mn[i];
    }

    size_t rowb = (size_t)g_rank[n] * 256;
    unsigned hi, lo;
    split_pair(mean[0], mean[1], hi, lo);
    g_Agh[rowb + 2 * lane] = hi;     g_Agl[rowb + 2 * lane] = lo;
    split_pair(mean[2], mean[3], hi, lo);
    g_Agh[rowb + 2 * lane + 1] = hi; g_Agl[rowb + 2 * lane + 1] = lo;
    split_pair(mxa[0], mxa[1], hi, lo);
    g_Agh[rowb + 64 + 2 * lane] = hi;     g_Agl[rowb + 64 + 2 * lane] = lo;
    split_pair(mxa[2], mxa[3], hi, lo);
    g_Agh[rowb + 64 + 2 * lane + 1] = hi; g_Agl[rowb + 64 + 2 * lane + 1] = lo;
    split_pair(mna[0], mna[1], hi, lo);
    g_Agh[rowb + 128 + 2 * lane] = hi;     g_Agl[rowb + 128 + 2 * lane] = lo;
    split_pair(mna[2], mna[3], hi, lo);
    g_Agh[rowb + 128 + 2 * lane + 1] = hi; g_Agl[rowb + 128 + 2 * lane + 1] = lo;
    split_pair(stdv[0], stdv[1], hi, lo);
    g_Agh[rowb + 192 + 2 * lane] = hi;     g_Agl[rowb + 192 + 2 * lane] = lo;
    split_pair(stdv[2], stdv[3], hi, lo);
    g_Agh[rowb + 192 + 2 * lane + 1] = hi; g_Agl[rowb + 192 + 2 * lane + 1] = lo;
}

// ---------------- bf16x3 GEMM, degree-bucketed, 3-stage pipeline -------------
__global__ __launch_bounds__(256, 2) void gemm_deg_kernel(
        const unsigned* __restrict__ WhImg, const unsigned* __restrict__ WcImg,
        const float* __restrict__ bias, float* __restrict__ hout,
        int write_split) {
    int b = blockIdx.x;
    if (b >= g_nblk[0]) return;
    extern __shared__ unsigned smem_u[];
    const uint32_t sbase = smem_u32(smem_u);

    const int row0 = g_blk_row0[b];
    const int blkend = g_blk_end[b];
    const unsigned* Wc = WcImg + (size_t)g_blk_deg[b] * 16 * 4096;

    const int tid = threadIdx.x;
    const int lane = tid & 31, wid = tid >> 5;
    const int warp_m = wid >> 2;   // 0..1 (32 rows)
    const int warp_n = wid & 3;    // 0..3 (32 cols)
    const int lr = lane >> 2, lc = lane & 3;
    const int lg = lane >> 3, l8 = lane & 7;
    const int a_row = ((lg & 1) << 3) + l8;
    const int a_col = (lg >> 1) << 2;
    const int b_row = ((lg >> 1) << 3) + l8;
    const int b_col = (lg & 1) << 2;
    const int a_base = (warp_m * 32 + a_row) * 20 + a_col;
    const int b_base = 2560 + (warp_n * 32 + b_row) * 20 + b_col;

    float acc[2][4][4];
    #pragma unroll
    for (int mt = 0; mt < 2; mt++)
        #pragma unroll
        for (int nt = 0; nt < 4; nt++)
            #pragma unroll
            for (int e = 0; e < 4; e++) acc[mt][nt][e] = 0.f;

    auto load_stage = [&](int j, int slot) {
        uint32_t base = sbase + slot * (STGU * 4);
        const unsigned *Ah, *Al, *Bsrc;
        int K2, coff;
        if (j < 4) {
            Ah = g_Hh; Al = g_Hl; K2 = 64; coff = j * 16;
            Bsrc = WhImg + (size_t)j * 4096;
        } else {
            Ah = g_Agh; Al = g_Agl; K2 = 256; coff = (j - 4) * 16;
            Bsrc = Wc + (size_t)(j - 4) * 4096;
        }
        #pragma unroll
        for (int c0 = 0; c0 < 6; c0++) {
            int c = c0 * 256 + tid;
            uint32_t dst;
            const unsigned* src;
            if (c < 512) {
                int half = (c >= 256) ? 1 : 0;
                int rem = c - half * 256;
                int r = rem >> 2, q = rem & 3;
                int slotr = min(row0 + r, blkend - 1);
                src = (half ? Al : Ah) + (size_t)slotr * K2 + coff + q * 4;
                dst = base + (half * 1280 + r * 20 + q * 4) * 4;
            } else {
                int cb = c - 512;
                int half = cb >> 9;
                int rem = cb & 511;
                int r = rem >> 2, q = rem & 3;
                src = Bsrc + half * 2048 + r * 16 + q * 4;
                dst = base + (2560 + half * 2560 + r * 20 + q * 4) * 4;
            }
            cp16(dst, src);
        }
        CP_COMMIT();
    };

    load_stage(0, 0);
    load_stage(1, 1);

    for (int j = 0; j < NJ; j++) {
        CP_WAIT1();          // stage j complete (<=1 younger group pending)
        __syncthreads();
        if (j + 2 < NJ) load_stage(j + 2, (j + 2) % NSTG);
        else CP_COMMIT();    // keep pending-group accounting aligned

        uint32_t st = sbase + (j % NSTG) * (STGU * 4);
        #pragma unroll
        for (int kb = 0; kb < 16; kb += 8) {
            unsigned ah[2][4], al[2][4];
            #pragma unroll
            for (int mt = 0; mt < 2; mt++) {
                uint32_t ad = st + (uint32_t)(a_base + mt * 320 + kb) * 4;
                ldsm4(ah[mt][0], ah[mt][1], ah[mt][2], ah[mt][3], ad);
                ldsm4(al[mt][0], al[mt][1], al[mt][2], al[mt][3], ad + 1280 * 4);
            }
            #pragma unroll
            for (int p = 0; p < 2; p++) {
                unsigned bh[4], bl[4];
                uint32_t bp = st + (uint32_t)(b_base + p * 320 + kb) * 4;
                ldsm4(bh[0], bh[1], bh[2], bh[3], bp);
                ldsm4(bl[0], bl[1], bl[2], bl[3], bp + 2560 * 4);
                #pragma unroll
                for (int q = 0; q < 2; q++) {
                    int nt = 2 * p + q;
                    #pragma unroll
                    for (int mt = 0; mt < 2; mt++) {
                        mma_bf16(acc[mt][nt], ah[mt], &bh[2 * q]);
                        mma_bf16(acc[mt][nt], al[mt], &bh[2 * q]);
                        mma_bf16(acc[mt][nt], ah[mt], &bl[2 * q]);
                    }
                }
            }
        }
    }

    // ---- epilogue: bias + relu, scatter to node order, optional h-image -----
    #pragma unroll
    for (int mt = 0; mt < 2; mt++)
        #pragma unroll
        for (int nt = 0; nt < 4; nt++) {
            int col0 = warp_n * 32 + nt * 8 + 2 * lc;
            float b0 = bias[col0], b1 = bias[col0 + 1];
            #pragma unroll
            for (int rh = 0; rh < 2; rh++) {
                int slot = row0 + warp_m * 32 + mt * 16 + lr + rh * 8;
                if (slot >= blkend) continue;
                int node = g_s2n[slot];
                int e0 = rh * 2;
                float2 v;
                v.x = fmaxf(acc[mt][nt][e0] + b0, 0.f);
                v.y = fmaxf(acc[mt][nt][e0 + 1] + b1, 0.f);
                *(float2*)&hout[(size_t)node * DH + col0] = v;
                if (write_split) {
                    unsigned hi, lo;
                    split_pair(v.x, v.y, hi, lo);
                    g_Hh[(size_t)slot * 64 + (col0 >> 1)] = hi;
                    g_Hl[(size_t)slot * 64 + (col0 >> 1)] = lo;
                }
            }
        }
}

// ---------------- pooling + bn/fc --------------------------------------------
#define POOL_NB 256
__global__ __launch_bounds__(128) void pool_kernel(
        const float* __restrict__ h, const int* __restrict__ batch) {
    int n0 = blockIdx.x * POOL_NB;
    int t = threadIdx.x;
    int nend = min(n0 + POOL_NB, NN);
    int cnt = nend - n0;
    __shared__ int sbm[POOL_NB];
    for (int i = t; i < cnt; i += 128) sbm[i] = batch[n0 + i];
    __syncthreads();
    float acc = 0.f;
    int cur = sbm[0];
    for (int i = 0; i < cnt; i++) {
        int b = sbm[i];
        if (b != cur) {
            atomicAdd(&g_pool[cur * DH + t], acc);
            acc = 0.f; cur = b;
        }
        acc += h[(size_t)(n0 + i) * DH + t];
    }
    atomicAdd(&g_pool[cur * DH + t], acc);
}

__global__ __launch_bounds__(512) void bnfc_kernel(
        const float* __restrict__ gamma, const float* __restrict__ beta,
        const float* __restrict__ fcW, const float* __restrict__ fcb,
        float* __restrict__ out) {
    __shared__ float sp[NG * DH];
    int t = threadIdx.x;
    for (int i = t; i < NG * DH; i += 512) sp[i] = g_pool[i];
    __syncthreads();
    if (t < 128) {
        float m = 0.f;
        #pragma unroll 4
        for (int g = 0; g < NG; g++) m += sp[g * DH + t];
        m *= (1.f / NG);
        float v = 0.f;
        #pragma unroll 4
        for (int g = 0; g < NG; g++) { float d = sp[g * DH + t] - m; v += d * d; }
        v *= (1.f / NG);
        float rs = rsqrtf(v + 1e-5f);
        float ga = gamma[t], be = beta[t];
        for (int g = 0; g < NG; g++)
            sp[g * DH + t] = (sp[g * DH + t] - m) * rs * ga + be;
    }
    __syncthreads();
    for (int i = t; i < NG * DLAT; i += 512) {
        int g = i / DLAT, jj = i % DLAT;
        float s = fcb[jj];
        #pragma unroll 8
        for (int c = 0; c < DH; c++) s += sp[g * DH + c] * fcW[c * DLAT + jj];
        out[i] = s;
    }
}

// ---------------- launch ------------------------------------------------------
extern "C" void kernel_launch(void* const* d_in, const int* in_sizes, int n_in,
                              void* d_out, int out_size) {
    const float* x     = (const float*)d_in[0];
    const int*   ei    = (const int*)d_in[1];
    const int*   batch = (const int*)d_in[2];
    const float* W0 = (const float*)d_in[3];  const float* b0 = (const float*)d_in[4];
    const float* W1 = (const float*)d_in[5];  const float* b1 = (const float*)d_in[6];
    const float* W2 = (const float*)d_in[7];  const float* b2 = (const float*)d_in[8];
    const float* gamma = (const float*)d_in[9];
    const float* beta  = (const float*)d_in[10];
    const float* fcW   = (const float*)d_in[11];
    const float* fcb   = (const float*)d_in[12];
    float* out = (float*)d_out;

    void *p_deg, *p_delta, *p_pool, *p_h0, *p_h1, *p_wh, *p_wc;
    cudaGetSymbolAddress(&p_deg,   g_deg);
    cudaGetSymbolAddress(&p_delta, g_delta);
    cudaGetSymbolAddress(&p_pool,  g_pool);
    cudaGetSymbolAddress(&p_h0,    g_h0);
    cudaGetSymbolAddress(&p_h1,    g_h1);
    cudaGetSymbolAddress(&p_wh,    g_WhImg);
    cudaGetSymbolAddress(&p_wc,    g_WcImg);
    float* h0 = (float*)p_h0;
    float* h1 = (float*)p_h1;
    unsigned* whimg = (unsigned*)p_wh;
    unsigned* wcimg = (unsigned*)p_wc;

    cudaFuncSetAttribute(gemm_deg_kernel,
                         cudaFuncAttributeMaxDynamicSharedMemorySize, SMEM_BYTES);

    cudaMemsetAsync(p_deg,   0, NN * sizeof(int));
    cudaMemsetAsync(p_delta, 0, sizeof(float));
    cudaMemsetAsync(p_pool,  0, NG * DH * sizeof(float));

    int eblocks = (NE + 1023) / 1024;
    int sblocks = (NN + 1023) / 1024;
    hist_kernel<<<eblocks, 1024>>>(ei);
    scan1_kernel<<<sblocks, 1024>>>();
    scan2_kernel<<<1, 32>>>(sblocks);
    scan3_kernel<<<sblocks, 1024>>>();
    scatter_kernel<<<eblocks, 1024>>>(ei);
    delta_dhist_kernel<<<(NN + 255) / 256, 256>>>();
    dscan_blkmap_kernel<<<1, 32>>>();
    rank_kernel<<<(NN + 255) / 256, 256>>>();

    // W images (single launch each, layer = blockIdx.z)
    const size_t WHL = 4 * 4096;
    const size_t WCL = (size_t)MAXD * 16 * 4096;
    whsplit_kernel<<<dim3((4 * 2048 + 255) / 256, 1, 3), 256>>>(W0, W1, W2, whimg);
    wcomb_kernel<<<dim3(MAXD, 32, 3), 256>>>(W0, W1, W2, wcimg);

    xsplit_kernel<<<(NN * 64 + 255) / 256, 256>>>(x);

    int ablocks = (NN + 7) / 8;   // 6250

    // layer 0
    agg_kernel<<<ablocks, 256>>>(x);
    gemm_deg_kernel<<<MAXB, 256, SMEM_BYTES>>>(whimg, wcimg, b0, h0, 1);
    // layer 1
    agg_kernel<<<ablocks, 256>>>(h0);
    gemm_deg_kernel<<<MAXB, 256, SMEM_BYTES>>>(whimg + WHL, wcimg + WCL, b1, h1, 1);
    // layer 2
    agg_kernel<<<ablocks, 256>>>(h1);
    gemm_deg_kernel<<<MAXB, 256, SMEM_BYTES>>>(whimg + 2 * WHL, wcimg + 2 * WCL,
                                               b2, h0, 0);

    pool_kernel<<<(NN + POOL_NB - 1) / POOL_NB, 128>>>(h0, batch);
    bnfc_kernel<<<1, 512>>>(gamma, beta, fcW, fcb, out);
}